// round 14
// baseline (speedup 1.0000x reference)
#include <cuda_runtime.h>
#include <cuda_fp16.h>
#include <cstdint>
#include <math.h>

// ---------------- problem constants ----------------
#define NN   16384
#define MM   65536
#define E1N  131072
#define E2N  131072
#define ENCD 512
#define DECD 256
#define HCN  8
#define HIDN 1365
#define HIDP 1408

typedef __half f16;

// ---------------- fp32 scratch ----------------
static __device__ float s_root_ctx[NN * DECD];
static __device__ float s_a_src[MM * HCN];
static __device__ float s_a_tgt[NN * HCN];
static __device__ float s_den1[NN * HCN];
static __device__ float s_agg1[(size_t)NN * ENCD];
static __device__ float s_x1[(size_t)NN * ENCD];
static __device__ float s_q[(size_t)NN * ENCD];
static __device__ float s_den2[NN * HCN];
static __device__ float s_agg2[(size_t)NN * ENCD];
static __device__ float s_x2[(size_t)NN * ENCD];
static __device__ float s_gate[(size_t)NN * HIDP];
static __device__ float s_o[(size_t)NN * ENCD];

// ---------------- CSR scratch ----------------
static __device__ int s_cnt1[NN], s_off1[NN + 1], s_cur1[NN], s_perm1[E1N];
static __device__ int s_cnt2[NN], s_off2[NN + 1], s_cur2[NN], s_perm2[E2N];

// ---------------- fp16 scratch ----------------
static __device__ f16 s_rbh[(size_t)NN * ENCD];
static __device__ f16 s_fbh[(size_t)MM * DECD];
static __device__ f16 s_x8h[(size_t)8 * NN * DECD];
static __device__ f16 s_x1h[(size_t)NN * ENCD];
static __device__ f16 s_kh[(size_t)NN * ENCD];
static __device__ f16 s_vh[(size_t)NN * ENCD];
static __device__ f16 s_x2h[(size_t)NN * ENCD];
static __device__ f16 s_gsh[(size_t)NN * HIDP];
static __device__ f16 s_xfh[(size_t)NN * ENCD],  s_xfl[(size_t)NN * ENCD];
// weights (hi-only)
static __device__ f16 s_wxh[ENCD * DECD];
static __device__ f16 s_wchp[DECD * 1024];
static __device__ f16 s_wqh[ENCD * 1536];
static __device__ f16 s_wgh[ENCD * HIDP];
static __device__ f16 s_wuh[ENCD * HIDP];
static __device__ f16 s_woh[HIDP * ENCD];
static __device__ f16 s_wfh[ENCD * DECD];

__device__ __forceinline__ float4 ld4(const float* p) {
    return *reinterpret_cast<const float4*>(p);
}

__device__ __forceinline__ void split2(float f, f16& h, f16& l) {
    h = __float2half_rn(f);
    l = __float2half_rn(f - __half2float(h));
}

__device__ __forceinline__ float4 ld4h(const f16* p) {
    uint2 raw = *reinterpret_cast<const uint2*>(p);
    float2 a = __half22float2(*reinterpret_cast<__half2*>(&raw.x));
    float2 b = __half22float2(*reinterpret_cast<__half2*>(&raw.y));
    return make_float4(a.x, a.y, b.x, b.y);
}

// ================= baseline-PTX tensor helpers =================
__device__ __forceinline__ uint32_t smem_u32(const void* p) {
    uint32_t a;
    asm("{ .reg .u64 t; cvta.to.shared.u64 t, %1; cvt.u32.u64 %0, t; }" : "=r"(a) : "l"(p));
    return a;
}
#define CP16(dst, src) asm volatile("cp.async.cg.shared.global [%0], [%1], 16;" :: "r"(dst), "l"(src))
#define CP_COMMIT()    asm volatile("cp.async.commit_group;" ::: "memory")
#define CP_WAIT1()     asm volatile("cp.async.wait_group 1;" ::: "memory")

#define LDSMX4(r, a) \
    asm volatile("ldmatrix.sync.aligned.m8n8.x4.shared.b16 {%0,%1,%2,%3}, [%4];" \
        : "=r"((r)[0]), "=r"((r)[1]), "=r"((r)[2]), "=r"((r)[3]) : "r"(a))
#define LDSMX4T(r, a) \
    asm volatile("ldmatrix.sync.aligned.m8n8.x4.trans.shared.b16 {%0,%1,%2,%3}, [%4];" \
        : "=r"((r)[0]), "=r"((r)[1]), "=r"((r)[2]), "=r"((r)[3]) : "r"(a))

#define MMAH(d, a, b0, b1) \
    asm volatile("mma.sync.aligned.m16n8k16.row.col.f32.f16.f16.f32 " \
        "{%0,%1,%2,%3},{%4,%5,%6,%7},{%8,%9},{%0,%1,%2,%3};" \
        : "+f"((d)[0]), "+f"((d)[1]), "+f"((d)[2]), "+f"((d)[3]) \
        : "r"((a)[0]), "r"((a)[1]), "r"((a)[2]), "r"((a)[3]), "r"(b0), "r"(b1))

// smem per stage: AH[128x80B] (AL iff TERMS==2) BH[32x272B]; 3 stages
#define SMEM_T2 (3 * 29184)
#define SMEM_T1 (3 * 18944)

// ============ fp16 HMMA GEMM, 3-stage cp.async pipeline: C = A@B (+bias) ============
template<int EPI, bool GATHER, int TERMS>
__global__ __launch_bounds__(256, 2)
void hgemm(const f16* __restrict__ Ahi, const f16* __restrict__ Alo,
           const f16* __restrict__ Bhi,
           const float* __restrict__ bias,
           float* __restrict__ C0, float* __restrict__ C1, float* __restrict__ C2,
           const float* __restrict__ emul, const int* __restrict__ rowidx,
           int Nc, int K)
{
    constexpr uint32_t OFF_AL = 10240;
    constexpr uint32_t OFF_BH = (TERMS == 2) ? 20480u : 10240u;
    constexpr uint32_t BUFB   = (TERMS == 2) ? 29184u : 18944u;

    extern __shared__ __align__(16) char smc[];
    const uint32_t smb = smem_u32(smc);
    const int tid  = threadIdx.x;
    const int wid  = tid >> 5;
    const int lane = tid & 31;
    const int warp_m = wid >> 2;
    const int warp_n = wid & 3;
    const long bm = (long)blockIdx.y * 128;
    const long bn = (long)blockIdx.x * 128;
    const long aoff = (EPI == 4) ? (long)blockIdx.x * NN : 0;

    long g0 = aoff + bm + (tid >> 2), g1 = g0 + 64;
    if (GATHER) {
        g0 = (long)rowidx[bm + (tid >> 2)];
        g1 = (long)rowidx[bm + (tid >> 2) + 64];
    }
    const f16* pAh0 = Ahi + g0 * (long)K + (tid & 3) * 8;
    const f16* pAh1 = Ahi + g1 * (long)K + (tid & 3) * 8;
    const f16* pAl0 = (TERMS == 2) ? (Alo + g0 * (long)K + (tid & 3) * 8) : pAh0;
    const f16* pAl1 = (TERMS == 2) ? (Alo + g1 * (long)K + (tid & 3) * 8) : pAh1;
    const f16* pBh  = Bhi + (long)(tid >> 4) * Nc + bn + (tid & 15) * 8;

    const uint32_t dA  = (uint32_t)((tid >> 2) * 80 + (tid & 3) * 16);
    const uint32_t dA2 = dA + 64 * 80;
    const uint32_t dB  = (uint32_t)((tid >> 4) * 272 + (tid & 15) * 16);
    const uint32_t dB2 = dB + 16 * 272;

    float acc[4][4][4];
    #pragma unroll
    for (int a = 0; a < 4; a++)
        #pragma unroll
        for (int b = 0; b < 4; b++)
            #pragma unroll
            for (int c = 0; c < 4; c++) acc[a][b][c] = 0.f;

    const int nch = K >> 5;

    #pragma unroll
    for (int s = 0; s < 2; s++) {
        const int kt = s << 5;
        const uint32_t base = smb + (uint32_t)s * BUFB;
        CP16(base + dA,           pAh0 + kt);
        CP16(base + dA2,          pAh1 + kt);
        if (TERMS == 2) {
            CP16(base + OFF_AL + dA,  pAl0 + kt);
            CP16(base + OFF_AL + dA2, pAl1 + kt);
        }
        const f16* q0 = pBh + (long)kt * Nc;
        CP16(base + OFF_BH + dB,  q0);
        CP16(base + OFF_BH + dB2, q0 + 16L * Nc);
        CP_COMMIT();
    }

    int buf = 0, nbuf = 2;
    for (int ch = 0; ch < nch; ch++) {
        CP_WAIT1();
        __syncthreads();
        if (ch + 2 < nch) {
            const int kt = (ch + 2) << 5;
            const uint32_t base = smb + (uint32_t)nbuf * BUFB;
            CP16(base + dA,           pAh0 + kt);
            CP16(base + dA2,          pAh1 + kt);
            if (TERMS == 2) {
                CP16(base + OFF_AL + dA,  pAl0 + kt);
                CP16(base + OFF_AL + dA2, pAl1 + kt);
            }
            const f16* q0 = pBh + (long)kt * Nc;
            CP16(base + OFF_BH + dB,  q0);
            CP16(base + OFF_BH + dB2, q0 + 16L * Nc);
        }
        CP_COMMIT();

        const uint32_t abase = smb + (uint32_t)buf * BUFB;
        const uint32_t bbase = abase + OFF_BH;

        #pragma unroll
        for (int ks = 0; ks < 2; ks++) {
            uint32_t ah[4][4], al[4][4];
            #pragma unroll
            for (int mt = 0; mt < 4; mt++) {
                uint32_t ad = abase
                    + (uint32_t)((warp_m * 64 + mt * 16 + (lane & 15)) * 80)
                    + (uint32_t)((ks * 16 + ((lane >> 4) << 3)) << 1);
                LDSMX4(ah[mt], ad);
                if (TERMS == 2) LDSMX4(al[mt], ad + OFF_AL);
            }
            uint32_t bh[2][4];
            #pragma unroll
            for (int p = 0; p < 2; p++) {
                int kk = ks * 16 + (lane & 7) + ((lane >> 3) & 1) * 8;
                int nn = warp_n * 32 + p * 16 + ((lane >> 4) & 1) * 8;
                uint32_t bd = bbase + (uint32_t)(kk * 272 + nn * 2);
                LDSMX4T(bh[p], bd);
            }
            #pragma unroll
            for (int mt = 0; mt < 4; mt++)
                #pragma unroll
                for (int nt = 0; nt < 4; nt++) {
                    const int p = nt >> 1, h = (nt & 1) * 2;
                    MMAH(acc[mt][nt], ah[mt], bh[p][h], bh[p][h + 1]);
                    if (TERMS == 2)
                        MMAH(acc[mt][nt], al[mt], bh[p][h], bh[p][h + 1]);
                }
        }
        buf = (buf == 2) ? 0 : buf + 1;
        nbuf = (nbuf == 2) ? 0 : nbuf + 1;
    }

    // ---- epilogue ----
    #pragma unroll
    for (int mt = 0; mt < 4; mt++) {
        #pragma unroll
        for (int nt = 0; nt < 4; nt++) {
            long r0 = bm + warp_m * 64 + mt * 16 + (lane >> 2);
            int  c0 = (int)bn + warp_n * 32 + nt * 8 + (lane & 3) * 2;
            #pragma unroll
            for (int half = 0; half < 2; half++) {
                long r = r0 + half * 8;
                float v0 = acc[mt][nt][half * 2 + 0];
                float v1 = acc[mt][nt][half * 2 + 1];
                if (bias) { v0 += bias[c0]; v1 += bias[c0 + 1]; }
                if (EPI == 1) {
                    #pragma unroll
                    for (int e = 0; e < 2; e++) {
                        int gc = c0 + e;
                        float vv = e ? v1 : v0;
                        int h = gc / 192, rr = gc % 192;
                        int d = rr / 3, t = rr % 3;
                        long oidx = r * 512 + h * 64 + d;
                        if (t == 0) C0[oidx] = vv;
                        else if (t == 1) reinterpret_cast<f16*>(C1)[oidx] = __float2half_rn(vv);
                        else reinterpret_cast<f16*>(C2)[oidx] = __float2half_rn(vv);
                    }
                } else if (EPI == 3) {
                    float gv0 = emul[r * (long)Nc + c0];
                    float gv1 = emul[r * (long)Nc + c0 + 1];
                    v0 *= gv0 / (1.f + expf(-gv0));
                    v1 *= gv1 / (1.f + expf(-gv1));
                    uint32_t hp = (uint32_t)__half_as_ushort(__float2half_rn(v0))
                                | ((uint32_t)__half_as_ushort(__float2half_rn(v1)) << 16);
                    *reinterpret_cast<uint32_t*>(
                        reinterpret_cast<f16*>(C0) + r * (long)Nc + c0) = hp;
                } else if (EPI == 4) {
                    int c_local = c0 - (int)bn;
                    if (c_local < 64) {
                        float2 o = make_float2(v0, v1);
                        *reinterpret_cast<float2*>(
                            C0 + r * 512 + blockIdx.x * 64 + c_local) = o;
                    }
                } else {
                    if (EPI == 2) {
                        v0 *= emul[r * (long)Nc + c0];
                        v1 *= emul[r * (long)Nc + c0 + 1];
                    }
                    float2 o = make_float2(v0, v1);
                    *reinterpret_cast<float2*>(C0 + r * (long)Nc + c0) = o;
                }
            }
        }
    }
}

// ---------------- conversions ----------------
__global__ void k_hi(const float* __restrict__ in, f16* __restrict__ hi, long n4) {
    long i = (long)blockIdx.x * 256 + threadIdx.x;
    if (i >= n4) return;
    long idx = i * 4;
    float4 v = ld4(in + idx);
    f16 h[4];
    h[0] = __float2half_rn(v.x); h[1] = __float2half_rn(v.y);
    h[2] = __float2half_rn(v.z); h[3] = __float2half_rn(v.w);
    *reinterpret_cast<uint64_t*>(hi + idx) = *reinterpret_cast<uint64_t*>(h);
}

#define NWX 131072
#define NWQ 786432
#define NWF 131072
#define NWG 720896
#define NWO 720896
#define NWC 262144
#define CWX (NWX)
#define CWQ (CWX + NWQ)
#define CWF (CWQ + NWF)
#define CWG (CWF + NWG)
#define CWU (CWG + NWG)
#define CWO (CWU + NWO)
#define CWC (CWO + NWC)
__global__ void k_wconv(const float* __restrict__ Wx, const float* __restrict__ Wq,
                        const float* __restrict__ Wf, const float* __restrict__ Wg,
                        const float* __restrict__ Wu, const float* __restrict__ Wo,
                        const float* __restrict__ Wc,
                        f16* __restrict__ wxh, f16* __restrict__ wqh, f16* __restrict__ wfh,
                        f16* __restrict__ wgh, f16* __restrict__ wuh, f16* __restrict__ woh,
                        f16* __restrict__ wchp)
{
    int i = blockIdx.x * 256 + threadIdx.x;
    if (i < CWX) {
        wxh[i] = __float2half_rn(Wx[i]);
    } else if (i < CWQ) {
        int j = i - CWX; wqh[j] = __float2half_rn(Wq[j]);
    } else if (i < CWF) {
        int j = i - CWQ; wfh[j] = __float2half_rn(Wf[j]);
    } else if (i < CWG) {
        int j = i - CWF; int r = j / HIDP, c = j % HIDP;
        wgh[j] = __float2half_rn((c < HIDN) ? Wg[r * HIDN + c] : 0.f);
    } else if (i < CWU) {
        int j = i - CWG; int r = j / HIDP, c = j % HIDP;
        wuh[j] = __float2half_rn((c < HIDN) ? Wu[r * HIDN + c] : 0.f);
    } else if (i < CWO) {
        int j = i - CWU; int r = j / 512;
        woh[j] = __float2half_rn((r < HIDN) ? Wo[j] : 0.f);
    } else if (i < CWC) {
        int j = i - CWO; int r = j >> 10, cc = j & 1023;
        int head = cc >> 7, c0 = cc & 127;
        wchp[j] = __float2half_rn((c0 < 64) ? Wc[r * 512 + head * 64 + c0] : 0.f);
    }
}

// ---------------- CSR build ----------------
__global__ void k_zero_cnt(int* __restrict__ c1, int* __restrict__ c2) {
    int i = blockIdx.x * 256 + threadIdx.x;
    if (i < NN) { c1[i] = 0; c2[i] = 0; }
}

__global__ void k_hist2(const int* __restrict__ e1i, const int* __restrict__ e2i,
                        int* __restrict__ c1, int* __restrict__ c2) {
    int e = blockIdx.x * 256 + threadIdx.x;
    if (e < E1N) {
        atomicAdd(&c1[e1i[e]], 1);
        atomicAdd(&c2[e2i[e]], 1);
    }
}

__global__ void k_scan2(const int* __restrict__ c1, int* __restrict__ o1, int* __restrict__ u1,
                        const int* __restrict__ c2, int* __restrict__ o2, int* __restrict__ u2) {
    const int* cnt = blockIdx.x ? c2 : c1;
    int* off = blockIdx.x ? o2 : o1;
    int* cur = blockIdx.x ? u2 : u1;
    __shared__ int wsum[32];
    int t = threadIdx.x;
    int base = t * 16;
    int loc[16];
    int s = 0;
    #pragma unroll
    for (int i = 0; i < 16; i++) { loc[i] = s; s += cnt[base + i]; }
    int lane = t & 31, wd = t >> 5;
    int v = s;
    #pragma unroll
    for (int o = 1; o < 32; o <<= 1) {
        int u = __shfl_up_sync(0xffffffffu, v, o);
        if (lane >= o) v += u;
    }
    if (lane == 31) wsum[wd] = v;
    __syncthreads();
    if (wd == 0) {
        int wv = wsum[lane];
        #pragma unroll
        for (int o = 1; o < 32; o <<= 1) {
            int u = __shfl_up_sync(0xffffffffu, wv, o);
            if (lane >= o) wv += u;
        }
        wsum[lane] = wv;
    }
    __syncthreads();
    int prefix = (v - s) + (wd > 0 ? wsum[wd - 1] : 0);
    #pragma unroll
    for (int i = 0; i < 16; i++) {
        int o = prefix + loc[i];
        off[base + i] = o;
        cur[base + i] = o;
    }
    if (t == 1023) off[NN] = prefix + s;
}

__global__ void k_bucket2(const int* __restrict__ e1i, int* __restrict__ u1, int* __restrict__ p1,
                          const int* __restrict__ e2i, int* __restrict__ u2, int* __restrict__ p2) {
    int e = blockIdx.x * 256 + threadIdx.x;
    if (e < E1N) {
        int pos = atomicAdd(&u1[e1i[e]], 1);
        p1[pos] = e;
        int pos2 = atomicAdd(&u2[e2i[e]], 1);
        p2[pos2] = e;
    }
}

// ---- phase-1 gather, scores inline, fp16 fb, depth-1 prefetch ----
__global__ void k_gather1(const int* __restrict__ off, const int* __restrict__ perm,
                          const int* __restrict__ ej,
                          const float* __restrict__ a_src, const float* __restrict__ a_tgt,
                          const float* __restrict__ b_attn,
                          const f16* __restrict__ fbh16,
                          f16* __restrict__ x8h, float* __restrict__ den)
{
    const int n = blockIdx.x;
    const int t = threadIdx.x;     // 128
    const int dg = (t & 63) * 4;
    const int hb = (t >> 6) * 4;
    __shared__ int sj[128];
    float acc[4][4];
    #pragma unroll
    for (int a = 0; a < 4; a++)
        #pragma unroll
        for (int b = 0; b < 4; b++) acc[a][b] = 0.f;
    float dw0 = 0.f, dw1 = 0.f, dw2 = 0.f, dw3 = 0.f;

    float4 at4 = ld4(a_tgt + (size_t)n * 8 + hb);
    float4 b4  = ld4(b_attn + hb);
    at4.x += b4.x; at4.y += b4.y; at4.z += b4.z; at4.w += b4.w;

    const int s0 = off[n], s1 = off[n + 1];
    for (int p0 = s0; p0 < s1; p0 += 128) {
        int m = s1 - p0; if (m > 128) m = 128;
        __syncthreads();
        if (t < m) sj[t] = ej[perm[p0 + t]];
        __syncthreads();
        // prefetch edge 0
        float4 as_n, v_n;
        {
            int j0 = sj[0];
            as_n = ld4(a_src + (size_t)j0 * 8 + hb);
            v_n  = ld4h(fbh16 + (size_t)j0 * 256 + dg);
        }
        for (int q = 0; q < m; q++) {
            float4 as4 = as_n, v4 = v_n;
            if (q + 1 < m) {
                int jn = sj[q + 1];
                as_n = ld4(a_src + (size_t)jn * 8 + hb);
                v_n  = ld4h(fbh16 + (size_t)jn * 256 + dg);
            }
            float s0f = as4.x + at4.x; s0f = s0f > 0.f ? s0f : 0.2f * s0f;
            float s1f = as4.y + at4.y; s1f = s1f > 0.f ? s1f : 0.2f * s1f;
            float s2f = as4.z + at4.z; s2f = s2f > 0.f ? s2f : 0.2f * s2f;
            float s3f = as4.w + at4.w; s3f = s3f > 0.f ? s3f : 0.2f * s3f;
            float w0 = expf(s0f), w1 = expf(s1f), w2 = expf(s2f), w3 = expf(s3f);
            acc[0][0] += w0*v4.x; acc[0][1] += w0*v4.y; acc[0][2] += w0*v4.z; acc[0][3] += w0*v4.w;
            acc[1][0] += w1*v4.x; acc[1][1] += w1*v4.y; acc[1][2] += w1*v4.z; acc[1][3] += w1*v4.w;
            acc[2][0] += w2*v4.x; acc[2][1] += w2*v4.y; acc[2][2] += w2*v4.z; acc[2][3] += w2*v4.w;
            acc[3][0] += w3*v4.x; acc[3][1] += w3*v4.y; acc[3][2] += w3*v4.z; acc[3][3] += w3*v4.w;
            dw0 += w0; dw1 += w1; dw2 += w2; dw3 += w3;
        }
    }
    #pragma unroll
    for (int hh = 0; hh < 4; hh++) {
        size_t base = ((size_t)(hb + hh) * NN + n) * 256 + dg;
        f16 h[4];
        h[0] = __float2half_rn(acc[hh][0]); h[1] = __float2half_rn(acc[hh][1]);
        h[2] = __float2half_rn(acc[hh][2]); h[3] = __float2half_rn(acc[hh][3]);
        *reinterpret_cast<uint64_t*>(x8h + base) = *reinterpret_cast<uint64_t*>(h);
    }
    if ((t & 63) == 0) {
        float4 d4 = make_float4(dw0, dw1, dw2, dw3);
        *reinterpret_cast<float4*>(den + (size_t)n * 8 + hb) = d4;
    }
}

// ---- phase-2 fused gather: scores + weighted v sum (k, v fp16), depth-1 prefetch ----
__global__ void k_gather2f(const int* __restrict__ off, const int* __restrict__ perm,
                           const int* __restrict__ ej, const float* __restrict__ attr,
                           const float* __restrict__ q, const f16* __restrict__ kh,
                           const f16* __restrict__ vh,
                           float* __restrict__ agg, float* __restrict__ den)
{
    const int n = blockIdx.x;
    const int t = threadIdx.x;           // 128
    const int h = t >> 4;
    const int c = t * 4;
    const int dg = (t & 15) * 4;
    __shared__ int sj[128];
    __shared__ int se[128];
    float4 qr = ld4(q + (size_t)n * 512 + c);
    float4 acc = make_float4(0.f, 0.f, 0.f, 0.f);
    float dsum = 0.f;
    const int s0 = off[n], s1 = off[n + 1];
    for (int p0 = s0; p0 < s1; p0 += 128) {
        int m = s1 - p0; if (m > 128) m = 128;
        __syncthreads();
        if (t < m) {
            int e = perm[p0 + t];
            se[t] = e;
            sj[t] = ej[e];
        }
        __syncthreads();
        // prefetch edge 0
        float4 a_n, k_n, v_n;
        {
            int j0 = sj[0], e0 = se[0];
            a_n = ld4(attr + (size_t)e0 * 64 + dg);
            k_n = ld4h(kh + (size_t)j0 * 512 + c);
            v_n = ld4h(vh + (size_t)j0 * 512 + c);
        }
        for (int qq = 0; qq < m; qq++) {
            float4 a4 = a_n, k4 = k_n, v4 = v_n;
            if (qq + 1 < m) {
                int jn = sj[qq + 1], en = se[qq + 1];
                a_n = ld4(attr + (size_t)en * 64 + dg);
                k_n = ld4h(kh + (size_t)jn * 512 + c);
                v_n = ld4h(vh + (size_t)jn * 512 + c);
            }
            float p = qr.x * k4.x * a4.x + qr.y * k4.y * a4.y
                    + qr.z * k4.z * a4.z + qr.w * k4.w * a4.w;
            p += __shfl_xor_sync(0xffffffffu, p, 1);
            p += __shfl_xor_sync(0xffffffffu, p, 2);
            p += __shfl_xor_sync(0xffffffffu, p, 4);
            p += __shfl_xor_sync(0xffffffffu, p, 8);
            float ww = expf(p * 0.125f);
            acc.x += ww * v4.x; acc.y += ww * v4.y;
            acc.z += ww * v4.z; acc.w += ww * v4.w;
            dsum += ww;
        }
    }
    *reinterpret_cast<float4*>(agg + (size_t)n * 512 + c) = acc;
    if ((t & 15) == 0) den[n * 8 + h] = dsum;
}

// ---------------- skinny projection ----------------
__global__ void k_proj8(const float* __restrict__ A, const float* __restrict__ W,
                        float* __restrict__ out)
{
    __shared__ float Wsh[256 * 8];
    int t = threadIdx.x;
    for (int idx = t; idx < 2048; idx += 256) Wsh[idx] = W[idx];
    __syncthreads();
    int warp = t >> 5, lane = t & 31;
    long row = (long)blockIdx.x * 8 + warp;
    const float* a = A + row * 256;
    float acc[8] = {0.f,0.f,0.f,0.f,0.f,0.f,0.f,0.f};
    for (int kk = lane; kk < 256; kk += 32) {
        float av = a[kk];
        #pragma unroll
        for (int h = 0; h < 8; h++) acc[h] += av * Wsh[kk * 8 + h];
    }
    #pragma unroll
    for (int h = 0; h < 8; h++)
        #pragma unroll
        for (int off = 16; off; off >>= 1)
            acc[h] += __shfl_xor_sync(0xffffffffu, acc[h], off);
    if (lane == 0) {
        #pragma unroll
        for (int h = 0; h < 8; h++) out[row * 8 + h] = acc[h];
    }
}

// ---------------- rmsnorms ----------------
__global__ void k_rmsnorm1(const float* __restrict__ base, const float* __restrict__ num,
                           const float* __restrict__ den, const float* __restrict__ a_tgt,
                           const float* __restrict__ b_attn, const float* __restrict__ bc,
                           const float* __restrict__ g,
                           float* __restrict__ out, f16* __restrict__ oh) {
    int n = blockIdx.x;
    int t = threadIdx.x;
    float v[4]; float ss = 0.f;
    #pragma unroll
    for (int u2 = 0; u2 < 4; u2++) {
        int c = t + u2 * 128;
        int h = c >> 6;
        float s = a_tgt[n * 8 + h] + b_attn[h];
        s = s > 0.f ? s : 0.2f * s;
        float e0 = expf(s);
        float d = den[n * 8 + h] + e0;
        size_t idx = (size_t)n * 512 + c;
        float bval = base[idx];
        float add = (num[idx] + den[n * 8 + h] * bc[c] + e0 * bval) / d;
        float val = bval + add;
        v[u2] = val; ss += val * val;
    }
    #pragma unroll
    for (int off = 16; off; off >>= 1) ss += __shfl_xor_sync(0xffffffffu, ss, off);
    __shared__ float red[4];
    if ((t & 31) == 0) red[t >> 5] = ss;
    __syncthreads();
    float tot = red[0] + red[1] + red[2] + red[3];
    float r = rsqrtf(tot * (1.0f / 512.0f) + 1e-6f);
    #pragma unroll
    for (int u2 = 0; u2 < 4; u2++) {
        int c = t + u2 * 128;
        float o = v[u2] * r * g[c];
        size_t idx = (size_t)n * 512 + c;
        out[idx] = o;
        oh[idx] = __float2half_rn(o);
    }
}

__global__ void k_rmsnorm(const float* __restrict__ base, const float* __restrict__ num,
                          const float* __restrict__ den, const float* __restrict__ g,
                          float* __restrict__ out, f16* __restrict__ oh, f16* __restrict__ ol) {
    int n = blockIdx.x;
    int t = threadIdx.x;
    float v[4]; float ss = 0.f;
    #pragma unroll
    for (int u2 = 0; u2 < 4; u2++) {
        int c = t + u2 * 128;
        float a = num[(size_t)n * 512 + c];
        float add;
        if (den) { float d = den[n * 8 + (c >> 6)]; add = (d != 0.f) ? a / d : 0.f; }
        else add = a;
        float val = base[(size_t)n * 512 + c] + add;
        v[u2] = val; ss += val * val;
    }
    #pragma unroll
    for (int off = 16; off; off >>= 1) ss += __shfl_xor_sync(0xffffffffu, ss, off);
    __shared__ float red[4];
    if ((t & 31) == 0) red[t >> 5] = ss;
    __syncthreads();
    float tot = red[0] + red[1] + red[2] + red[3];
    float r = rsqrtf(tot * (1.0f / 512.0f) + 1e-6f);
    #pragma unroll
    for (int u2 = 0; u2 < 4; u2++) {
        int c = t + u2 * 128;
        float o = v[u2] * r * g[c];
        size_t idx = (size_t)n * 512 + c;
        out[idx] = o;
        if (oh) {
            if (ol) { f16 h, l; split2(o, h, l); oh[idx] = h; ol[idx] = l; }
            else oh[idx] = __float2half_rn(o);
        }
    }
}

// ---------------- host ----------------
#define SYM(p, s) cudaGetSymbolAddress((void**)&(p), s)

extern "C" void kernel_launch(void* const* d_in, const int* in_sizes, int n_in,
                              void* d_out, int out_size) {
    (void)in_sizes; (void)n_in; (void)out_size;
    const float* root   = (const float*)d_in[0];
    const float* fb     = (const float*)d_in[1];
    const int*   fbi    = (const int*)d_in[2];
    const int*   e1j = fbi;       const int* e1i = fbi + E1N;
    const float* fmaps  = (const float*)d_in[3];
    const int*   r2f    = (const int*)d_in[4];
    const int*   rei    = (const int*)d_in[5];
    const int*   e2j = rei;       const int* e2i = rei + E2N;
    const float* attr   = (const float*)d_in[6];
    const float* W_c2x  = (const float*)d_in[7];
    const float* b_c2x  = (const float*)d_in[8];
    const float* W_x2c  = (const float*)d_in[9];
    const float* b_x2c  = (const float*)d_in[10];
    const float* W_attn = (const float*)d_in[11];
    const float* b_attn = (const float*)d_in[12];
    const float* W_qkv  = (const float*)d_in[13];
    const float* b_qkv  = (const float*)d_in[14];
    const float* W_gate = (const float*)d_in[15];
    const float* W_up   = (const float*)d_in[16];
    const float* W_out  = (const float*)d_in[17];
    const float* W_fr   = (const float*)d_in[18];
    const float* b_fr   = (const float*)d_in[19];
    const float* gn     = (const float*)d_in[20];
    const float* gr     = (const float*)d_in[21];
    const float* gf     = (const float*)d_in[22];

    float* outx = (float*)d_out;
    float* outf = outx + (size_t)NN * ENCD;

    float *p_root_ctx, *p_a_src, *p_a_tgt, *p_den1, *p_agg1, *p_x1;
    float *p_q, *p_den2, *p_agg2, *p_x2, *p_gate, *p_o;
    SYM(p_root_ctx, s_root_ctx); SYM(p_a_src, s_a_src); SYM(p_a_tgt, s_a_tgt);
    SYM(p_den1, s_den1);
    SYM(p_agg1, s_agg1);         SYM(p_x1, s_x1);
    SYM(p_q, s_q);
    SYM(p_den2, s_den2); SYM(p_agg2, s_agg2); SYM(p_x2, s_x2);
    SYM(p_gate, s_gate); SYM(p_o, s_o);

    int *cnt1,*off1,*cur1,*perm1,*cnt2,*off2,*cur2,*perm2;
    SYM(cnt1, s_cnt1); SYM(off1, s_off1); SYM(cur1, s_cur1); SYM(perm1, s_perm1);
    SYM(cnt2, s_cnt2); SYM(off2, s_off2); SYM(cur2, s_cur2); SYM(perm2, s_perm2);

    f16 *rbh,*fbh,*x8h,*x1h,*kh,*vh,*x2h,*gsh,*xfh,*xfl;
    f16 *wxh,*wchp,*wqh,*wgh,*wuh,*woh,*wfh;
    SYM(rbh, s_rbh); SYM(fbh, s_fbh); SYM(x8h, s_x8h);
    SYM(x1h, s_x1h); SYM(kh, s_kh); SYM(vh, s_vh);
    SYM(x2h, s_x2h); SYM(gsh, s_gsh);
    SYM(xfh, s_xfh); SYM(xfl, s_xfl);
    SYM(wxh, s_wxh); SYM(wchp, s_wchp); SYM(wqh, s_wqh);
    SYM(wgh, s_wgh); SYM(wuh, s_wuh); SYM(woh, s_woh); SYM(wfh, s_wfh);

    cudaFuncSetAttribute((const void*)hgemm<0,false,1>, cudaFuncAttributeMaxDynamicSharedMemorySize, SMEM_T1);
    cudaFuncSetAttribute((const void*)hgemm<1,false,1>, cudaFuncAttributeMaxDynamicSharedMemorySize, SMEM_T1);
    cudaFuncSetAttribute((const void*)hgemm<3,false,1>, cudaFuncAttributeMaxDynamicSharedMemorySize, SMEM_T1);
    cudaFuncSetAttribute((const void*)hgemm<4,false,1>, cudaFuncAttributeMaxDynamicSharedMemorySize, SMEM_T1);
    cudaFuncSetAttribute((const void*)hgemm<2,true,2>,  cudaFuncAttributeMaxDynamicSharedMemorySize, SMEM_T2);

    // ---- prologue ----
    k_wconv<<<CWC/256, 256>>>(W_x2c, W_qkv, W_fr, W_gate, W_up, W_out, W_c2x,
                              wxh, wqh, wfh, wgh, wuh, woh, wchp);
    k_hi<<<((long)NN*ENCD/4 + 255)/256, 256>>>(root, rbh, (long)NN*ENCD/4);
    k_zero_cnt<<<NN/256, 256>>>(cnt1, cnt2);
    hgemm<0,false,1><<<dim3(2,128), 256, SMEM_T1>>>(rbh, nullptr, wxh, b_x2c,
        p_root_ctx, nullptr, nullptr, nullptr, nullptr, DECD, ENCD);
    k_hi<<<((long)MM*DECD/4 + 255)/256, 256>>>(fb, fbh, (long)MM*DECD/4);
    k_hist2<<<E1N/256, 256>>>(e1i, e2i, cnt1, cnt2);
    k_scan2<<<2, 1024>>>(cnt1, off1, cur1, cnt2, off2, cur2);
    k_bucket2<<<E1N/256, 256>>>(e1i, cur1, perm1, e2i, cur2, perm2);

    // ---- HGAT attention projections ----
    k_proj8<<<MM/8, 256>>>(fb, W_attn, p_a_src);
    k_proj8<<<NN/8, 256>>>(p_root_ctx, W_attn + 256*8, p_a_tgt);

    // ---- HGAT: gather (scores inline, fp16 fb), hoisted GEMM ----
    k_gather1<<<NN, 128>>>(off1, perm1, e1j, p_a_src, p_a_tgt, b_attn, fbh,
        x8h, p_den1);
    hgemm<4,false,1><<<dim3(8,128), 256, SMEM_T1>>>(x8h, nullptr, wchp, nullptr,
        p_agg1, nullptr, nullptr, nullptr, nullptr, 1024, DECD);
    k_rmsnorm1<<<NN, 128>>>(root, p_agg1, p_den1, p_a_tgt, b_attn, b_c2x,
        gn, p_x1, x1h);

    // ---- Self-MHA ----
    hgemm<1,false,1><<<dim3(12,128), 256, SMEM_T1>>>(x1h, nullptr, wqh, b_qkv,
        p_q, (float*)kh, (float*)vh, nullptr, nullptr, 1536, ENCD);
    k_gather2f<<<NN, 128>>>(off2, perm2, e2j, attr, p_q, kh, vh, p_agg2, p_den2);
    k_rmsnorm<<<NN, 128>>>(p_x1, p_agg2, p_den2, gr, p_x2, x2h, nullptr);

    // ---- SwiGLU FFN ----
    hgemm<0,false,1><<<dim3(HIDP/128,128), 256, SMEM_T1>>>(x2h, nullptr, wgh, nullptr,
        p_gate, nullptr, nullptr, nullptr, nullptr, HIDP, ENCD);
    hgemm<3,false,1><<<dim3(HIDP/128,128), 256, SMEM_T1>>>(x2h, nullptr, wuh, nullptr,
        (float*)gsh, nullptr, nullptr, p_gate, nullptr, HIDP, ENCD);
    hgemm<0,false,1><<<dim3(4,128), 256, SMEM_T1>>>(gsh, nullptr, woh, nullptr,
        p_o, nullptr, nullptr, nullptr, nullptr, ENCD, HIDP);
    k_rmsnorm<<<NN, 128>>>(p_x2, p_o, nullptr, gf, outx, xfh, xfl);

    // ---- fringe decode ----
    hgemm<2,true,2><<<dim3(2,128), 256, SMEM_T2>>>(xfh, xfl, wfh, b_fr,
        outf, nullptr, nullptr, fmaps, r2f, DECD, ENCD);
}

// round 15
// speedup vs baseline: 1.0471x; 1.0471x over previous
#include <cuda_runtime.h>
#include <cuda_fp16.h>
#include <cstdint>
#include <math.h>

// ---------------- problem constants ----------------
#define NN   16384
#define MM   65536
#define E1N  131072
#define E2N  131072
#define ENCD 512
#define DECD 256
#define HCN  8
#define HIDN 1365
#define HIDP 1408

typedef __half f16;

// ---------------- fp32 scratch ----------------
static __device__ float s_root_ctx[NN * DECD];
static __device__ float s_a_src[MM * HCN];
static __device__ float s_a_tgt[NN * HCN];
static __device__ float s_den1[NN * HCN];
static __device__ float s_agg1[(size_t)NN * ENCD];
static __device__ float s_x1[(size_t)NN * ENCD];
static __device__ float s_q[(size_t)NN * ENCD];
static __device__ float s_den2[NN * HCN];
static __device__ float s_agg2[(size_t)NN * ENCD];
static __device__ float s_x2[(size_t)NN * ENCD];
static __device__ float s_gate[(size_t)NN * HIDP];
static __device__ float s_o[(size_t)NN * ENCD];

// ---------------- CSR scratch ----------------
static __device__ int s_cnt1[NN], s_off1[NN + 1], s_cur1[NN], s_perm1[E1N];
static __device__ int s_cnt2[NN], s_off2[NN + 1], s_cur2[NN], s_perm2[E2N];

// ---------------- fp16 scratch ----------------
static __device__ f16 s_rbh[(size_t)NN * ENCD];
static __device__ f16 s_fbh[(size_t)MM * DECD];
static __device__ f16 s_x8h[(size_t)8 * NN * DECD];
static __device__ f16 s_x1h[(size_t)NN * ENCD];
static __device__ f16 s_kh[(size_t)NN * ENCD];
static __device__ f16 s_vh[(size_t)NN * ENCD];
static __device__ f16 s_x2h[(size_t)NN * ENCD];
static __device__ f16 s_gsh[(size_t)NN * HIDP];
static __device__ f16 s_xfh[(size_t)NN * ENCD];
// weights (hi-only)
static __device__ f16 s_wxh[ENCD * DECD];
static __device__ f16 s_wchp[DECD * 1024];
static __device__ f16 s_wqh[ENCD * 1536];
static __device__ f16 s_wgh[ENCD * HIDP];
static __device__ f16 s_wuh[ENCD * HIDP];
static __device__ f16 s_woh[HIDP * ENCD];
static __device__ f16 s_wfh[ENCD * DECD];

__device__ __forceinline__ float4 ld4(const float* p) {
    return *reinterpret_cast<const float4*>(p);
}

__device__ __forceinline__ float4 ld4h(const f16* p) {
    uint2 raw = *reinterpret_cast<const uint2*>(p);
    float2 a = __half22float2(*reinterpret_cast<__half2*>(&raw.x));
    float2 b = __half22float2(*reinterpret_cast<__half2*>(&raw.y));
    return make_float4(a.x, a.y, b.x, b.y);
}

// ================= baseline-PTX tensor helpers =================
__device__ __forceinline__ uint32_t smem_u32(const void* p) {
    uint32_t a;
    asm("{ .reg .u64 t; cvta.to.shared.u64 t, %1; cvt.u32.u64 %0, t; }" : "=r"(a) : "l"(p));
    return a;
}
#define CP16(dst, src) asm volatile("cp.async.cg.shared.global [%0], [%1], 16;" :: "r"(dst), "l"(src))
#define CP_COMMIT()    asm volatile("cp.async.commit_group;" ::: "memory")
#define CP_WAIT1()     asm volatile("cp.async.wait_group 1;" ::: "memory")

#define LDSMX4(r, a) \
    asm volatile("ldmatrix.sync.aligned.m8n8.x4.shared.b16 {%0,%1,%2,%3}, [%4];" \
        : "=r"((r)[0]), "=r"((r)[1]), "=r"((r)[2]), "=r"((r)[3]) : "r"(a))
#define LDSMX4T(r, a) \
    asm volatile("ldmatrix.sync.aligned.m8n8.x4.trans.shared.b16 {%0,%1,%2,%3}, [%4];" \
        : "=r"((r)[0]), "=r"((r)[1]), "=r"((r)[2]), "=r"((r)[3]) : "r"(a))

#define MMAH(d, a, b0, b1) \
    asm volatile("mma.sync.aligned.m16n8k16.row.col.f32.f16.f16.f32 " \
        "{%0,%1,%2,%3},{%4,%5,%6,%7},{%8,%9},{%0,%1,%2,%3};" \
        : "+f"((d)[0]), "+f"((d)[1]), "+f"((d)[2]), "+f"((d)[3]) \
        : "r"((a)[0]), "r"((a)[1]), "r"((a)[2]), "r"((a)[3]), "r"(b0), "r"(b1))

// smem per stage: AH[128x80B] BH[32x272B]; 3 stages
#define SMEM_T1 (3 * 18944)

// ============ fp16 HMMA GEMM, 3-stage cp.async pipeline: C = A@B (+bias) ============
// EPI: 0 plain, 1 qkv de-interleave (q fp32, k/v fp16), 2 fringe (*emul),
//      3 silu-fuse (hi out), 4 per-head HGAT. GATHER: A row = rowidx[row].
template<int EPI, bool GATHER>
__global__ __launch_bounds__(256, 2)
void hgemm(const f16* __restrict__ Ahi,
           const f16* __restrict__ Bhi,
           const float* __restrict__ bias,
           float* __restrict__ C0, float* __restrict__ C1, float* __restrict__ C2,
           const float* __restrict__ emul, const int* __restrict__ rowidx,
           int Nc, int K)
{
    constexpr uint32_t OFF_BH = 10240u;
    constexpr uint32_t BUFB   = 18944u;

    extern __shared__ __align__(16) char smc[];
    const uint32_t smb = smem_u32(smc);
    const int tid  = threadIdx.x;
    const int wid  = tid >> 5;
    const int lane = tid & 31;
    const int warp_m = wid >> 2;
    const int warp_n = wid & 3;
    const long bm = (long)blockIdx.y * 128;
    const long bn = (long)blockIdx.x * 128;
    const long aoff = (EPI == 4) ? (long)blockIdx.x * NN : 0;

    long g0 = aoff + bm + (tid >> 2), g1 = g0 + 64;
    if (GATHER) {
        g0 = (long)rowidx[bm + (tid >> 2)];
        g1 = (long)rowidx[bm + (tid >> 2) + 64];
    }
    const f16* pAh0 = Ahi + g0 * (long)K + (tid & 3) * 8;
    const f16* pAh1 = Ahi + g1 * (long)K + (tid & 3) * 8;
    const f16* pBh  = Bhi + (long)(tid >> 4) * Nc + bn + (tid & 15) * 8;

    const uint32_t dA  = (uint32_t)((tid >> 2) * 80 + (tid & 3) * 16);
    const uint32_t dA2 = dA + 64 * 80;
    const uint32_t dB  = (uint32_t)((tid >> 4) * 272 + (tid & 15) * 16);
    const uint32_t dB2 = dB + 16 * 272;

    float acc[4][4][4];
    #pragma unroll
    for (int a = 0; a < 4; a++)
        #pragma unroll
        for (int b = 0; b < 4; b++)
            #pragma unroll
            for (int c = 0; c < 4; c++) acc[a][b][c] = 0.f;

    const int nch = K >> 5;

    #pragma unroll
    for (int s = 0; s < 2; s++) {
        const int kt = s << 5;
        const uint32_t base = smb + (uint32_t)s * BUFB;
        CP16(base + dA,           pAh0 + kt);
        CP16(base + dA2,          pAh1 + kt);
        const f16* q0 = pBh + (long)kt * Nc;
        CP16(base + OFF_BH + dB,  q0);
        CP16(base + OFF_BH + dB2, q0 + 16L * Nc);
        CP_COMMIT();
    }

    int buf = 0, nbuf = 2;
    for (int ch = 0; ch < nch; ch++) {
        CP_WAIT1();
        __syncthreads();
        if (ch + 2 < nch) {
            const int kt = (ch + 2) << 5;
            const uint32_t base = smb + (uint32_t)nbuf * BUFB;
            CP16(base + dA,           pAh0 + kt);
            CP16(base + dA2,          pAh1 + kt);
            const f16* q0 = pBh + (long)kt * Nc;
            CP16(base + OFF_BH + dB,  q0);
            CP16(base + OFF_BH + dB2, q0 + 16L * Nc);
        }
        CP_COMMIT();

        const uint32_t abase = smb + (uint32_t)buf * BUFB;
        const uint32_t bbase = abase + OFF_BH;

        #pragma unroll
        for (int ks = 0; ks < 2; ks++) {
            uint32_t ah[4][4];
            #pragma unroll
            for (int mt = 0; mt < 4; mt++) {
                uint32_t ad = abase
                    + (uint32_t)((warp_m * 64 + mt * 16 + (lane & 15)) * 80)
                    + (uint32_t)((ks * 16 + ((lane >> 4) << 3)) << 1);
                LDSMX4(ah[mt], ad);
            }
            uint32_t bh[2][4];
            #pragma unroll
            for (int p = 0; p < 2; p++) {
                int kk = ks * 16 + (lane & 7) + ((lane >> 3) & 1) * 8;
                int nn = warp_n * 32 + p * 16 + ((lane >> 4) & 1) * 8;
                uint32_t bd = bbase + (uint32_t)(kk * 272 + nn * 2);
                LDSMX4T(bh[p], bd);
            }
            #pragma unroll
            for (int mt = 0; mt < 4; mt++)
                #pragma unroll
                for (int nt = 0; nt < 4; nt++) {
                    const int p = nt >> 1, h = (nt & 1) * 2;
                    MMAH(acc[mt][nt], ah[mt], bh[p][h], bh[p][h + 1]);
                }
        }
        buf = (buf == 2) ? 0 : buf + 1;
        nbuf = (nbuf == 2) ? 0 : nbuf + 1;
    }

    // ---- epilogue ----
    #pragma unroll
    for (int mt = 0; mt < 4; mt++) {
        #pragma unroll
        for (int nt = 0; nt < 4; nt++) {
            long r0 = bm + warp_m * 64 + mt * 16 + (lane >> 2);
            int  c0 = (int)bn + warp_n * 32 + nt * 8 + (lane & 3) * 2;
            #pragma unroll
            for (int half = 0; half < 2; half++) {
                long r = r0 + half * 8;
                float v0 = acc[mt][nt][half * 2 + 0];
                float v1 = acc[mt][nt][half * 2 + 1];
                if (bias) { v0 += bias[c0]; v1 += bias[c0 + 1]; }
                if (EPI == 1) {
                    #pragma unroll
                    for (int e = 0; e < 2; e++) {
                        int gc = c0 + e;
                        float vv = e ? v1 : v0;
                        int h = gc / 192, rr = gc % 192;
                        int d = rr / 3, t = rr % 3;
                        long oidx = r * 512 + h * 64 + d;
                        if (t == 0) C0[oidx] = vv;
                        else if (t == 1) reinterpret_cast<f16*>(C1)[oidx] = __float2half_rn(vv);
                        else reinterpret_cast<f16*>(C2)[oidx] = __float2half_rn(vv);
                    }
                } else if (EPI == 3) {
                    float gv0 = emul[r * (long)Nc + c0];
                    float gv1 = emul[r * (long)Nc + c0 + 1];
                    v0 *= gv0 / (1.f + expf(-gv0));
                    v1 *= gv1 / (1.f + expf(-gv1));
                    uint32_t hp = (uint32_t)__half_as_ushort(__float2half_rn(v0))
                                | ((uint32_t)__half_as_ushort(__float2half_rn(v1)) << 16);
                    *reinterpret_cast<uint32_t*>(
                        reinterpret_cast<f16*>(C0) + r * (long)Nc + c0) = hp;
                } else if (EPI == 4) {
                    int c_local = c0 - (int)bn;
                    if (c_local < 64) {
                        float2 o = make_float2(v0, v1);
                        *reinterpret_cast<float2*>(
                            C0 + r * 512 + blockIdx.x * 64 + c_local) = o;
                    }
                } else {
                    if (EPI == 2) {
                        v0 *= emul[r * (long)Nc + c0];
                        v1 *= emul[r * (long)Nc + c0 + 1];
                    }
                    float2 o = make_float2(v0, v1);
                    *reinterpret_cast<float2*>(C0 + r * (long)Nc + c0) = o;
                }
            }
        }
    }
}

// ---------------- conversions ----------------
__global__ void k_hi(const float* __restrict__ in, f16* __restrict__ hi, long n4) {
    long i = (long)blockIdx.x * 256 + threadIdx.x;
    if (i >= n4) return;
    long idx = i * 4;
    float4 v = ld4(in + idx);
    f16 h[4];
    h[0] = __float2half_rn(v.x); h[1] = __float2half_rn(v.y);
    h[2] = __float2half_rn(v.z); h[3] = __float2half_rn(v.w);
    *reinterpret_cast<uint64_t*>(hi + idx) = *reinterpret_cast<uint64_t*>(h);
}

#define NWX 131072
#define NWQ 786432
#define NWF 131072
#define NWG 720896
#define NWO 720896
#define NWC 262144
#define CWX (NWX)
#define CWQ (CWX + NWQ)
#define CWF (CWQ + NWF)
#define CWG (CWF + NWG)
#define CWU (CWG + NWG)
#define CWO (CWU + NWO)
#define CWC (CWO + NWC)
__global__ void k_wconv(const float* __restrict__ Wx, const float* __restrict__ Wq,
                        const float* __restrict__ Wf, const float* __restrict__ Wg,
                        const float* __restrict__ Wu, const float* __restrict__ Wo,
                        const float* __restrict__ Wc,
                        f16* __restrict__ wxh, f16* __restrict__ wqh, f16* __restrict__ wfh,
                        f16* __restrict__ wgh, f16* __restrict__ wuh, f16* __restrict__ woh,
                        f16* __restrict__ wchp)
{
    int i = blockIdx.x * 256 + threadIdx.x;
    if (i < CWX) {
        wxh[i] = __float2half_rn(Wx[i]);
    } else if (i < CWQ) {
        int j = i - CWX; wqh[j] = __float2half_rn(Wq[j]);
    } else if (i < CWF) {
        int j = i - CWQ; wfh[j] = __float2half_rn(Wf[j]);
    } else if (i < CWG) {
        int j = i - CWF; int r = j / HIDP, c = j % HIDP;
        wgh[j] = __float2half_rn((c < HIDN) ? Wg[r * HIDN + c] : 0.f);
    } else if (i < CWU) {
        int j = i - CWG; int r = j / HIDP, c = j % HIDP;
        wuh[j] = __float2half_rn((c < HIDN) ? Wu[r * HIDN + c] : 0.f);
    } else if (i < CWO) {
        int j = i - CWU; int r = j / 512;
        woh[j] = __float2half_rn((r < HIDN) ? Wo[j] : 0.f);
    } else if (i < CWC) {
        int j = i - CWO; int r = j >> 10, cc = j & 1023;
        int head = cc >> 7, c0 = cc & 127;
        wchp[j] = __float2half_rn((c0 < 64) ? Wc[r * 512 + head * 64 + c0] : 0.f);
    }
}

// ---------------- CSR build ----------------
__global__ void k_zero_cnt(int* __restrict__ c1, int* __restrict__ c2) {
    int i = blockIdx.x * 256 + threadIdx.x;
    if (i < NN) { c1[i] = 0; c2[i] = 0; }
}

__global__ void k_hist2(const int* __restrict__ e1i, const int* __restrict__ e2i,
                        int* __restrict__ c1, int* __restrict__ c2) {
    int e = blockIdx.x * 256 + threadIdx.x;
    if (e < E1N) {
        atomicAdd(&c1[e1i[e]], 1);
        atomicAdd(&c2[e2i[e]], 1);
    }
}

__global__ void k_scan2(const int* __restrict__ c1, int* __restrict__ o1, int* __restrict__ u1,
                        const int* __restrict__ c2, int* __restrict__ o2, int* __restrict__ u2) {
    const int* cnt = blockIdx.x ? c2 : c1;
    int* off = blockIdx.x ? o2 : o1;
    int* cur = blockIdx.x ? u2 : u1;
    __shared__ int wsum[32];
    int t = threadIdx.x;
    int base = t * 16;
    int loc[16];
    int s = 0;
    #pragma unroll
    for (int i = 0; i < 16; i++) { loc[i] = s; s += cnt[base + i]; }
    int lane = t & 31, wd = t >> 5;
    int v = s;
    #pragma unroll
    for (int o = 1; o < 32; o <<= 1) {
        int u = __shfl_up_sync(0xffffffffu, v, o);
        if (lane >= o) v += u;
    }
    if (lane == 31) wsum[wd] = v;
    __syncthreads();
    if (wd == 0) {
        int wv = wsum[lane];
        #pragma unroll
        for (int o = 1; o < 32; o <<= 1) {
            int u = __shfl_up_sync(0xffffffffu, wv, o);
            if (lane >= o) wv += u;
        }
        wsum[lane] = wv;
    }
    __syncthreads();
    int prefix = (v - s) + (wd > 0 ? wsum[wd - 1] : 0);
    #pragma unroll
    for (int i = 0; i < 16; i++) {
        int o = prefix + loc[i];
        off[base + i] = o;
        cur[base + i] = o;
    }
    if (t == 1023) off[NN] = prefix + s;
}

__global__ void k_bucket2(const int* __restrict__ e1i, int* __restrict__ u1, int* __restrict__ p1,
                          const int* __restrict__ e2i, int* __restrict__ u2, int* __restrict__ p2) {
    int e = blockIdx.x * 256 + threadIdx.x;
    if (e < E1N) {
        int pos = atomicAdd(&u1[e1i[e]], 1);
        p1[pos] = e;
        int pos2 = atomicAdd(&u2[e2i[e]], 1);
        p2[pos2] = e;
    }
}

// ---- phase-1 gather, scores inline, fp16 fb (R13 form) ----
__global__ void k_gather1(const int* __restrict__ off, const int* __restrict__ perm,
                          const int* __restrict__ ej,
                          const float* __restrict__ a_src, const float* __restrict__ a_tgt,
                          const float* __restrict__ b_attn,
                          const f16* __restrict__ fbh16,
                          f16* __restrict__ x8h, float* __restrict__ den)
{
    const int n = blockIdx.x;
    const int t = threadIdx.x;     // 128
    const int dg = (t & 63) * 4;
    const int hb = (t >> 6) * 4;
    __shared__ int sj[128];
    float acc[4][4];
    #pragma unroll
    for (int a = 0; a < 4; a++)
        #pragma unroll
        for (int b = 0; b < 4; b++) acc[a][b] = 0.f;
    float dw0 = 0.f, dw1 = 0.f, dw2 = 0.f, dw3 = 0.f;

    float4 at4 = ld4(a_tgt + (size_t)n * 8 + hb);
    float4 b4  = ld4(b_attn + hb);
    at4.x += b4.x; at4.y += b4.y; at4.z += b4.z; at4.w += b4.w;

    const int s0 = off[n], s1 = off[n + 1];
    for (int p0 = s0; p0 < s1; p0 += 128) {
        int m = s1 - p0; if (m > 128) m = 128;
        __syncthreads();
        if (t < m) sj[t] = ej[perm[p0 + t]];
        __syncthreads();
        for (int q = 0; q < m; q++) {
            int j = sj[q];
            float4 as4 = ld4(a_src + (size_t)j * 8 + hb);
            float s0f = as4.x + at4.x; s0f = s0f > 0.f ? s0f : 0.2f * s0f;
            float s1f = as4.y + at4.y; s1f = s1f > 0.f ? s1f : 0.2f * s1f;
            float s2f = as4.z + at4.z; s2f = s2f > 0.f ? s2f : 0.2f * s2f;
            float s3f = as4.w + at4.w; s3f = s3f > 0.f ? s3f : 0.2f * s3f;
            float w0 = expf(s0f), w1 = expf(s1f), w2 = expf(s2f), w3 = expf(s3f);
            float4 v4 = ld4h(fbh16 + (size_t)j * 256 + dg);
            acc[0][0] += w0*v4.x; acc[0][1] += w0*v4.y; acc[0][2] += w0*v4.z; acc[0][3] += w0*v4.w;
            acc[1][0] += w1*v4.x; acc[1][1] += w1*v4.y; acc[1][2] += w1*v4.z; acc[1][3] += w1*v4.w;
            acc[2][0] += w2*v4.x; acc[2][1] += w2*v4.y; acc[2][2] += w2*v4.z; acc[2][3] += w2*v4.w;
            acc[3][0] += w3*v4.x; acc[3][1] += w3*v4.y; acc[3][2] += w3*v4.z; acc[3][3] += w3*v4.w;
            dw0 += w0; dw1 += w1; dw2 += w2; dw3 += w3;
        }
    }
    #pragma unroll
    for (int hh = 0; hh < 4; hh++) {
        size_t base = ((size_t)(hb + hh) * NN + n) * 256 + dg;
        f16 h[4];
        h[0] = __float2half_rn(acc[hh][0]); h[1] = __float2half_rn(acc[hh][1]);
        h[2] = __float2half_rn(acc[hh][2]); h[3] = __float2half_rn(acc[hh][3]);
        *reinterpret_cast<uint64_t*>(x8h + base) = *reinterpret_cast<uint64_t*>(h);
    }
    if ((t & 63) == 0) {
        float4 d4 = make_float4(dw0, dw1, dw2, dw3);
        *reinterpret_cast<float4*>(den + (size_t)n * 8 + hb) = d4;
    }
}

// ---- phase-2 fused gather (R13 form) ----
__global__ void k_gather2f(const int* __restrict__ off, const int* __restrict__ perm,
                           const int* __restrict__ ej, const float* __restrict__ attr,
                           const float* __restrict__ q, const f16* __restrict__ kh,
                           const f16* __restrict__ vh,
                           float* __restrict__ agg, float* __restrict__ den)
{
    const int n = blockIdx.x;
    const int t = threadIdx.x;           // 128
    const int h = t >> 4;
    const int c = t * 4;
    const int dg = (t & 15) * 4;
    __shared__ int sj[128];
    __shared__ int se[128];
    float4 qr = ld4(q + (size_t)n * 512 + c);
    float4 acc = make_float4(0.f, 0.f, 0.f, 0.f);
    float dsum = 0.f;
    const int s0 = off[n], s1 = off[n + 1];
    for (int p0 = s0; p0 < s1; p0 += 128) {
        int m = s1 - p0; if (m > 128) m = 128;
        __syncthreads();
        if (t < m) {
            int e = perm[p0 + t];
            se[t] = e;
            sj[t] = ej[e];
        }
        __syncthreads();
        for (int qq = 0; qq < m; qq++) {
            int j = sj[qq], e = se[qq];
            float4 a4 = ld4(attr + (size_t)e * 64 + dg);
            float4 k4 = ld4h(kh + (size_t)j * 512 + c);
            float p = qr.x * k4.x * a4.x + qr.y * k4.y * a4.y
                    + qr.z * k4.z * a4.z + qr.w * k4.w * a4.w;
            p += __shfl_xor_sync(0xffffffffu, p, 1);
            p += __shfl_xor_sync(0xffffffffu, p, 2);
            p += __shfl_xor_sync(0xffffffffu, p, 4);
            p += __shfl_xor_sync(0xffffffffu, p, 8);
            float ww = expf(p * 0.125f);
            float4 v4 = ld4h(vh + (size_t)j * 512 + c);
            acc.x += ww * v4.x; acc.y += ww * v4.y;
            acc.z += ww * v4.z; acc.w += ww * v4.w;
            dsum += ww;
        }
    }
    *reinterpret_cast<float4*>(agg + (size_t)n * 512 + c) = acc;
    if ((t & 15) == 0) den[n * 8 + h] = dsum;
}

// ---------------- merged skinny projections: a_src (fb) and a_tgt (root_ctx) ----------------
__global__ void k_proj8_both(const float* __restrict__ fb, const float* __restrict__ rc,
                             const float* __restrict__ W,
                             float* __restrict__ a_src, float* __restrict__ a_tgt)
{
    __shared__ float Wsh[256 * 8];
    int t = threadIdx.x;
    const bool second = blockIdx.x >= (MM / 8);
    const float* Wsrc = second ? (W + 256 * 8) : W;
    for (int idx = t; idx < 2048; idx += 256) Wsh[idx] = Wsrc[idx];
    __syncthreads();
    int warp = t >> 5, lane = t & 31;
    long rb = second ? ((long)(blockIdx.x - MM / 8) * 8) : ((long)blockIdx.x * 8);
    long row = rb + warp;
    const float* a = (second ? rc : fb) + row * 256;
    float* outp = second ? a_tgt : a_src;
    float acc[8] = {0.f,0.f,0.f,0.f,0.f,0.f,0.f,0.f};
    for (int kk = lane; kk < 256; kk += 32) {
        float av = a[kk];
        #pragma unroll
        for (int h = 0; h < 8; h++) acc[h] += av * Wsh[kk * 8 + h];
    }
    #pragma unroll
    for (int h = 0; h < 8; h++)
        #pragma unroll
        for (int off = 16; off; off >>= 1)
            acc[h] += __shfl_xor_sync(0xffffffffu, acc[h], off);
    if (lane == 0) {
        #pragma unroll
        for (int h = 0; h < 8; h++) outp[row * 8 + h] = acc[h];
    }
}

// ---------------- rmsnorms ----------------
__global__ void k_rmsnorm1(const float* __restrict__ base, const float* __restrict__ num,
                           const float* __restrict__ den, const float* __restrict__ a_tgt,
                           const float* __restrict__ b_attn, const float* __restrict__ bc,
                           const float* __restrict__ g,
                           float* __restrict__ out, f16* __restrict__ oh) {
    int n = blockIdx.x;
    int t = threadIdx.x;
    float v[4]; float ss = 0.f;
    #pragma unroll
    for (int u2 = 0; u2 < 4; u2++) {
        int c = t + u2 * 128;
        int h = c >> 6;
        float s = a_tgt[n * 8 + h] + b_attn[h];
        s = s > 0.f ? s : 0.2f * s;
        float e0 = expf(s);
        float d = den[n * 8 + h] + e0;
        size_t idx = (size_t)n * 512 + c;
        float bval = base[idx];
        float add = (num[idx] + den[n * 8 + h] * bc[c] + e0 * bval) / d;
        float val = bval + add;
        v[u2] = val; ss += val * val;
    }
    #pragma unroll
    for (int off = 16; off; off >>= 1) ss += __shfl_xor_sync(0xffffffffu, ss, off);
    __shared__ float red[4];
    if ((t & 31) == 0) red[t >> 5] = ss;
    __syncthreads();
    float tot = red[0] + red[1] + red[2] + red[3];
    float r = rsqrtf(tot * (1.0f / 512.0f) + 1e-6f);
    #pragma unroll
    for (int u2 = 0; u2 < 4; u2++) {
        int c = t + u2 * 128;
        float o = v[u2] * r * g[c];
        size_t idx = (size_t)n * 512 + c;
        out[idx] = o;
        oh[idx] = __float2half_rn(o);
    }
}

__global__ void k_rmsnorm(const float* __restrict__ base, const float* __restrict__ num,
                          const float* __restrict__ den, const float* __restrict__ g,
                          float* __restrict__ out, f16* __restrict__ oh) {
    int n = blockIdx.x;
    int t = threadIdx.x;
    float v[4]; float ss = 0.f;
    #pragma unroll
    for (int u2 = 0; u2 < 4; u2++) {
        int c = t + u2 * 128;
        float a = num[(size_t)n * 512 + c];
        float add;
        if (den) { float d = den[n * 8 + (c >> 6)]; add = (d != 0.f) ? a / d : 0.f; }
        else add = a;
        float val = base[(size_t)n * 512 + c] + add;
        v[u2] = val; ss += val * val;
    }
    #pragma unroll
    for (int off = 16; off; off >>= 1) ss += __shfl_xor_sync(0xffffffffu, ss, off);
    __shared__ float red[4];
    if ((t & 31) == 0) red[t >> 5] = ss;
    __syncthreads();
    float tot = red[0] + red[1] + red[2] + red[3];
    float r = rsqrtf(tot * (1.0f / 512.0f) + 1e-6f);
    #pragma unroll
    for (int u2 = 0; u2 < 4; u2++) {
        int c = t + u2 * 128;
        float o = v[u2] * r * g[c];
        size_t idx = (size_t)n * 512 + c;
        out[idx] = o;
        if (oh) oh[idx] = __float2half_rn(o);
    }
}

// ---------------- host ----------------
#define SYM(p, s) cudaGetSymbolAddress((void**)&(p), s)

extern "C" void kernel_launch(void* const* d_in, const int* in_sizes, int n_in,
                              void* d_out, int out_size) {
    (void)in_sizes; (void)n_in; (void)out_size;
    const float* root   = (const float*)d_in[0];
    const float* fb     = (const float*)d_in[1];
    const int*   fbi    = (const int*)d_in[2];
    const int*   e1j = fbi;       const int* e1i = fbi + E1N;
    const float* fmaps  = (const float*)d_in[3];
    const int*   r2f    = (const int*)d_in[4];
    const int*   rei    = (const int*)d_in[5];
    const int*   e2j = rei;       const int* e2i = rei + E2N;
    const float* attr   = (const float*)d_in[6];
    const float* W_c2x  = (const float*)d_in[7];
    const float* b_c2x  = (const float*)d_in[8];
    const float* W_x2c  = (const float*)d_in[9];
    const float* b_x2c  = (const float*)d_in[10];
    const float* W_attn = (const float*)d_in[11];
    const float* b_attn = (const float*)d_in[12];
    const float* W_qkv  = (const float*)d_in[13];
    const float* b_qkv  = (const float*)d_in[14];
    const float* W_gate = (const float*)d_in[15];
    const float* W_up   = (const float*)d_in[16];
    const float* W_out  = (const float*)d_in[17];
    const float* W_fr   = (const float*)d_in[18];
    const float* b_fr   = (const float*)d_in[19];
    const float* gn     = (const float*)d_in[20];
    const float* gr     = (const float*)d_in[21];
    const float* gf     = (const float*)d_in[22];

    float* outx = (float*)d_out;
    float* outf = outx + (size_t)NN * ENCD;

    float *p_root_ctx, *p_a_src, *p_a_tgt, *p_den1, *p_agg1, *p_x1;
    float *p_q, *p_den2, *p_agg2, *p_x2, *p_gate, *p_o;
    SYM(p_root_ctx, s_root_ctx); SYM(p_a_src, s_a_src); SYM(p_a_tgt, s_a_tgt);
    SYM(p_den1, s_den1);
    SYM(p_agg1, s_agg1);         SYM(p_x1, s_x1);
    SYM(p_q, s_q);
    SYM(p_den2, s_den2); SYM(p_agg2, s_agg2); SYM(p_x2, s_x2);
    SYM(p_gate, s_gate); SYM(p_o, s_o);

    int *cnt1,*off1,*cur1,*perm1,*cnt2,*off2,*cur2,*perm2;
    SYM(cnt1, s_cnt1); SYM(off1, s_off1); SYM(cur1, s_cur1); SYM(perm1, s_perm1);
    SYM(cnt2, s_cnt2); SYM(off2, s_off2); SYM(cur2, s_cur2); SYM(perm2, s_perm2);

    f16 *rbh,*fbh,*x8h,*x1h,*kh,*vh,*x2h,*gsh,*xfh;
    f16 *wxh,*wchp,*wqh,*wgh,*wuh,*woh,*wfh;
    SYM(rbh, s_rbh); SYM(fbh, s_fbh); SYM(x8h, s_x8h);
    SYM(x1h, s_x1h); SYM(kh, s_kh); SYM(vh, s_vh);
    SYM(x2h, s_x2h); SYM(gsh, s_gsh); SYM(xfh, s_xfh);
    SYM(wxh, s_wxh); SYM(wchp, s_wchp); SYM(wqh, s_wqh);
    SYM(wgh, s_wgh); SYM(wuh, s_wuh); SYM(woh, s_woh); SYM(wfh, s_wfh);

    cudaFuncSetAttribute((const void*)hgemm<0,false>, cudaFuncAttributeMaxDynamicSharedMemorySize, SMEM_T1);
    cudaFuncSetAttribute((const void*)hgemm<1,false>, cudaFuncAttributeMaxDynamicSharedMemorySize, SMEM_T1);
    cudaFuncSetAttribute((const void*)hgemm<2,true>,  cudaFuncAttributeMaxDynamicSharedMemorySize, SMEM_T1);
    cudaFuncSetAttribute((const void*)hgemm<3,false>, cudaFuncAttributeMaxDynamicSharedMemorySize, SMEM_T1);
    cudaFuncSetAttribute((const void*)hgemm<4,false>, cudaFuncAttributeMaxDynamicSharedMemorySize, SMEM_T1);

    // ---- prologue ----
    k_wconv<<<CWC/256, 256>>>(W_x2c, W_qkv, W_fr, W_gate, W_up, W_out, W_c2x,
                              wxh, wqh, wfh, wgh, wuh, woh, wchp);
    k_hi<<<((long)NN*ENCD/4 + 255)/256, 256>>>(root, rbh, (long)NN*ENCD/4);
    k_zero_cnt<<<NN/256, 256>>>(cnt1, cnt2);
    hgemm<0,false><<<dim3(2,128), 256, SMEM_T1>>>(rbh, wxh, b_x2c,
        p_root_ctx, nullptr, nullptr, nullptr, nullptr, DECD, ENCD);
    k_hi<<<((long)MM*DECD/4 + 255)/256, 256>>>(fb, fbh, (long)MM*DECD/4);
    k_hist2<<<E1N/256, 256>>>(e1i, e2i, cnt1, cnt2);
    k_scan2<<<2, 1024>>>(cnt1, off1, cur1, cnt2, off2, cur2);
    k_bucket2<<<E1N/256, 256>>>(e1i, cur1, perm1, e2i, cur2, perm2);

    // ---- HGAT attention projections (merged) ----
    k_proj8_both<<<MM/8 + NN/8, 256>>>(fb, p_root_ctx, W_attn, p_a_src, p_a_tgt);

    // ---- HGAT: gather (scores inline, fp16 fb), hoisted GEMM ----
    k_gather1<<<NN, 128>>>(off1, perm1, e1j, p_a_src, p_a_tgt, b_attn, fbh,
        x8h, p_den1);
    hgemm<4,false><<<dim3(8,128), 256, SMEM_T1>>>(x8h, wchp, nullptr,
        p_agg1, nullptr, nullptr, nullptr, nullptr, 1024, DECD);
    k_rmsnorm1<<<NN, 128>>>(root, p_agg1, p_den1, p_a_tgt, b_attn, b_c2x,
        gn, p_x1, x1h);

    // ---- Self-MHA ----
    hgemm<1,false><<<dim3(12,128), 256, SMEM_T1>>>(x1h, wqh, b_qkv,
        p_q, (float*)kh, (float*)vh, nullptr, nullptr, 1536, ENCD);
    k_gather2f<<<NN, 128>>>(off2, perm2, e2j, attr, p_q, kh, vh, p_agg2, p_den2);
    k_rmsnorm<<<NN, 128>>>(p_x1, p_agg2, p_den2, gr, p_x2, x2h);

    // ---- SwiGLU FFN ----
    hgemm<0,false><<<dim3(HIDP/128,128), 256, SMEM_T1>>>(x2h, wgh, nullptr,
        p_gate, nullptr, nullptr, nullptr, nullptr, HIDP, ENCD);
    hgemm<3,false><<<dim3(HIDP/128,128), 256, SMEM_T1>>>(x2h, wuh, nullptr,
        (float*)gsh, nullptr, nullptr, p_gate, nullptr, HIDP, ENCD);
    hgemm<0,false><<<dim3(4,128), 256, SMEM_T1>>>(gsh, woh, nullptr,
        p_o, nullptr, nullptr, nullptr, nullptr, ENCD, HIDP);
    k_rmsnorm<<<NN, 128>>>(p_x2, p_o, nullptr, gf, outx, xfh);

    // ---- fringe decode (1-term) ----
    hgemm<2,true><<<dim3(2,128), 256, SMEM_T1>>>(xfh, wfh, b_fr,
        outf, nullptr, nullptr, fmaps, r2f, DECD, ENCD);
}

// round 16
// speedup vs baseline: 1.1142x; 1.0641x over previous
#include <cuda_runtime.h>
#include <cuda_fp16.h>
#include <cstdint>
#include <math.h>

// ---------------- problem constants ----------------
#define NN   16384
#define MM   65536
#define E1N  131072
#define E2N  131072
#define ENCD 512
#define DECD 256
#define HCN  8
#define HIDN 1365
#define HIDP 1408

typedef __half f16;

// ---------------- fp32 scratch ----------------
static __device__ float s_root_ctx[NN * DECD];
static __device__ float s_a_src[MM * HCN];
static __device__ float s_a_tgt[NN * HCN];
static __device__ float s_den1[NN * HCN];
static __device__ float s_agg1[(size_t)NN * ENCD];
static __device__ float s_x1[(size_t)NN * ENCD];
static __device__ float s_q[(size_t)NN * ENCD];
static __device__ float s_den2[NN * HCN];
static __device__ float s_agg2[(size_t)NN * ENCD];
static __device__ float s_x2[(size_t)NN * ENCD];
static __device__ float s_o[(size_t)NN * ENCD];

// ---------------- CSR scratch ----------------
static __device__ int s_cnt1[NN], s_off1[NN + 1], s_cur1[NN], s_perm1[E1N];
static __device__ int s_cnt2[NN], s_off2[NN + 1], s_cur2[NN], s_perm2[E2N];

// ---------------- fp16 scratch ----------------
static __device__ f16 s_rbh[(size_t)NN * ENCD];
static __device__ f16 s_fbh[(size_t)MM * DECD];
static __device__ f16 s_x8h[(size_t)8 * NN * DECD];
static __device__ f16 s_x1h[(size_t)NN * ENCD];
static __device__ f16 s_kh[(size_t)NN * ENCD];
static __device__ f16 s_vh[(size_t)NN * ENCD];
static __device__ f16 s_x2h[(size_t)NN * ENCD];
static __device__ f16 s_gsh[(size_t)NN * HIDP];
static __device__ f16 s_xfh[(size_t)NN * ENCD];
// weights (hi-only)
static __device__ f16 s_wxh[ENCD * DECD];
static __device__ f16 s_wchp[DECD * 1024];
static __device__ f16 s_wqh[ENCD * 1536];
static __device__ f16 s_wgu[ENCD * 2 * HIDP];   // interleaved gate/up [512, 2816]
static __device__ f16 s_woh[HIDP * ENCD];
static __device__ f16 s_wfh[ENCD * DECD];

__device__ __forceinline__ float4 ld4(const float* p) {
    return *reinterpret_cast<const float4*>(p);
}

__device__ __forceinline__ float4 ld4h(const f16* p) {
    uint2 raw = *reinterpret_cast<const uint2*>(p);
    float2 a = __half22float2(*reinterpret_cast<__half2*>(&raw.x));
    float2 b = __half22float2(*reinterpret_cast<__half2*>(&raw.y));
    return make_float4(a.x, a.y, b.x, b.y);
}

// ================= baseline-PTX tensor helpers =================
__device__ __forceinline__ uint32_t smem_u32(const void* p) {
    uint32_t a;
    asm("{ .reg .u64 t; cvta.to.shared.u64 t, %1; cvt.u32.u64 %0, t; }" : "=r"(a) : "l"(p));
    return a;
}
#define CP16(dst, src) asm volatile("cp.async.cg.shared.global [%0], [%1], 16;" :: "r"(dst), "l"(src))
#define CP_COMMIT()    asm volatile("cp.async.commit_group;" ::: "memory")
#define CP_WAIT1()     asm volatile("cp.async.wait_group 1;" ::: "memory")

#define LDSMX4(r, a) \
    asm volatile("ldmatrix.sync.aligned.m8n8.x4.shared.b16 {%0,%1,%2,%3}, [%4];" \
        : "=r"((r)[0]), "=r"((r)[1]), "=r"((r)[2]), "=r"((r)[3]) : "r"(a))
#define LDSMX4T(r, a) \
    asm volatile("ldmatrix.sync.aligned.m8n8.x4.trans.shared.b16 {%0,%1,%2,%3}, [%4];" \
        : "=r"((r)[0]), "=r"((r)[1]), "=r"((r)[2]), "=r"((r)[3]) : "r"(a))

#define MMAH(d, a, b0, b1) \
    asm volatile("mma.sync.aligned.m16n8k16.row.col.f32.f16.f16.f32 " \
        "{%0,%1,%2,%3},{%4,%5,%6,%7},{%8,%9},{%0,%1,%2,%3};" \
        : "+f"((d)[0]), "+f"((d)[1]), "+f"((d)[2]), "+f"((d)[3]) \
        : "r"((a)[0]), "r"((a)[1]), "r"((a)[2]), "r"((a)[3]), "r"(b0), "r"(b1))

// smem per stage: AH[128x80B] BH[32x272B]; 3 stages
#define SMEM_T1 (3 * 18944)

// ============ fp16 HMMA GEMM, 3-stage cp.async pipeline: C = A@B (+bias) ============
// EPI: 0 plain, 1 qkv de-interleave (q fp32, k/v fp16), 2 fringe (*emul),
//      4 per-head HGAT, 5 gate/up interleaved + in-register SwiGLU -> fp16.
// GATHER: A row = rowidx[row].
template<int EPI, bool GATHER>
__global__ __launch_bounds__(256, 2)
void hgemm(const f16* __restrict__ Ahi,
           const f16* __restrict__ Bhi,
           const float* __restrict__ bias,
           float* __restrict__ C0, float* __restrict__ C1, float* __restrict__ C2,
           const float* __restrict__ emul, const int* __restrict__ rowidx,
           int Nc, int K)
{
    constexpr uint32_t OFF_BH = 10240u;
    constexpr uint32_t BUFB   = 18944u;

    extern __shared__ __align__(16) char smc[];
    const uint32_t smb = smem_u32(smc);
    const int tid  = threadIdx.x;
    const int wid  = tid >> 5;
    const int lane = tid & 31;
    const int warp_m = wid >> 2;
    const int warp_n = wid & 3;
    const long bm = (long)blockIdx.y * 128;
    const long bn = (long)blockIdx.x * 128;
    const long aoff = (EPI == 4) ? (long)blockIdx.x * NN : 0;

    long g0 = aoff + bm + (tid >> 2), g1 = g0 + 64;
    if (GATHER) {
        g0 = (long)rowidx[bm + (tid >> 2)];
        g1 = (long)rowidx[bm + (tid >> 2) + 64];
    }
    const f16* pAh0 = Ahi + g0 * (long)K + (tid & 3) * 8;
    const f16* pAh1 = Ahi + g1 * (long)K + (tid & 3) * 8;
    const f16* pBh  = Bhi + (long)(tid >> 4) * Nc + bn + (tid & 15) * 8;

    const uint32_t dA  = (uint32_t)((tid >> 2) * 80 + (tid & 3) * 16);
    const uint32_t dA2 = dA + 64 * 80;
    const uint32_t dB  = (uint32_t)((tid >> 4) * 272 + (tid & 15) * 16);
    const uint32_t dB2 = dB + 16 * 272;

    float acc[4][4][4];
    #pragma unroll
    for (int a = 0; a < 4; a++)
        #pragma unroll
        for (int b = 0; b < 4; b++)
            #pragma unroll
            for (int c = 0; c < 4; c++) acc[a][b][c] = 0.f;

    const int nch = K >> 5;

    #pragma unroll
    for (int s = 0; s < 2; s++) {
        const int kt = s << 5;
        const uint32_t base = smb + (uint32_t)s * BUFB;
        CP16(base + dA,           pAh0 + kt);
        CP16(base + dA2,          pAh1 + kt);
        const f16* q0 = pBh + (long)kt * Nc;
        CP16(base + OFF_BH + dB,  q0);
        CP16(base + OFF_BH + dB2, q0 + 16L * Nc);
        CP_COMMIT();
    }

    int buf = 0, nbuf = 2;
    for (int ch = 0; ch < nch; ch++) {
        CP_WAIT1();
        __syncthreads();
        if (ch + 2 < nch) {
            const int kt = (ch + 2) << 5;
            const uint32_t base = smb + (uint32_t)nbuf * BUFB;
            CP16(base + dA,           pAh0 + kt);
            CP16(base + dA2,          pAh1 + kt);
            const f16* q0 = pBh + (long)kt * Nc;
            CP16(base + OFF_BH + dB,  q0);
            CP16(base + OFF_BH + dB2, q0 + 16L * Nc);
        }
        CP_COMMIT();

        const uint32_t abase = smb + (uint32_t)buf * BUFB;
        const uint32_t bbase = abase + OFF_BH;

        #pragma unroll
        for (int ks = 0; ks < 2; ks++) {
            uint32_t ah[4][4];
            #pragma unroll
            for (int mt = 0; mt < 4; mt++) {
                uint32_t ad = abase
                    + (uint32_t)((warp_m * 64 + mt * 16 + (lane & 15)) * 80)
                    + (uint32_t)((ks * 16 + ((lane >> 4) << 3)) << 1);
                LDSMX4(ah[mt], ad);
            }
            uint32_t bh[2][4];
            #pragma unroll
            for (int p = 0; p < 2; p++) {
                int kk = ks * 16 + (lane & 7) + ((lane >> 3) & 1) * 8;
                int nn = warp_n * 32 + p * 16 + ((lane >> 4) & 1) * 8;
                uint32_t bd = bbase + (uint32_t)(kk * 272 + nn * 2);
                LDSMX4T(bh[p], bd);
            }
            #pragma unroll
            for (int mt = 0; mt < 4; mt++)
                #pragma unroll
                for (int nt = 0; nt < 4; nt++) {
                    const int p = nt >> 1, h = (nt & 1) * 2;
                    MMAH(acc[mt][nt], ah[mt], bh[p][h], bh[p][h + 1]);
                }
        }
        buf = (buf == 2) ? 0 : buf + 1;
        nbuf = (nbuf == 2) ? 0 : nbuf + 1;
    }

    // ---- epilogue ----
    #pragma unroll
    for (int mt = 0; mt < 4; mt++) {
        #pragma unroll
        for (int nt = 0; nt < 4; nt++) {
            long r0 = bm + warp_m * 64 + mt * 16 + (lane >> 2);
            int  c0 = (int)bn + warp_n * 32 + nt * 8 + (lane & 3) * 2;
            #pragma unroll
            for (int half = 0; half < 2; half++) {
                long r = r0 + half * 8;
                float v0 = acc[mt][nt][half * 2 + 0];
                float v1 = acc[mt][nt][half * 2 + 1];
                if (bias) { v0 += bias[c0]; v1 += bias[c0 + 1]; }
                if (EPI == 1) {
                    #pragma unroll
                    for (int e = 0; e < 2; e++) {
                        int gc = c0 + e;
                        float vv = e ? v1 : v0;
                        int h = gc / 192, rr = gc % 192;
                        int d = rr / 3, t = rr % 3;
                        long oidx = r * 512 + h * 64 + d;
                        if (t == 0) C0[oidx] = vv;
                        else if (t == 1) reinterpret_cast<f16*>(C1)[oidx] = __float2half_rn(vv);
                        else reinterpret_cast<f16*>(C2)[oidx] = __float2half_rn(vv);
                    }
                } else if (EPI == 5) {
                    // v0 = gate, v1 = up for hidden unit c0>>1
                    float o = (v0 / (1.f + expf(-v0))) * v1;
                    reinterpret_cast<f16*>(C0)[r * (long)(Nc >> 1) + (c0 >> 1)]
                        = __float2half_rn(o);
                } else if (EPI == 4) {
                    int c_local = c0 - (int)bn;
                    if (c_local < 64) {
                        float2 o = make_float2(v0, v1);
                        *reinterpret_cast<float2*>(
                            C0 + r * 512 + blockIdx.x * 64 + c_local) = o;
                    }
                } else {
                    if (EPI == 2) {
                        v0 *= emul[r * (long)Nc + c0];
                        v1 *= emul[r * (long)Nc + c0 + 1];
                    }
                    float2 o = make_float2(v0, v1);
                    *reinterpret_cast<float2*>(C0 + r * (long)Nc + c0) = o;
                }
            }
        }
    }
}

// ---------------- mega prep kernel: all weight conversions + input conversions + zero ----------------
#define NWX 131072
#define NWQ 786432
#define NWF 131072
#define NWGU (ENCD * 2 * HIDP)          // 1441792
#define NWO 720896
#define NWC 262144
#define CWX (NWX)
#define CWQ (CWX + NWQ)
#define CWF (CWQ + NWF)
#define CWGU (CWF + NWGU)
#define CWO (CWGU + NWO)
#define CWC (CWO + NWC)
#define CRT (CWC + NN * ENCD / 4)       // root hi, float4 granules
#define CFB (CRT + MM * DECD / 4)       // fb hi, float4 granules
#define CZ  (CFB + NN)                  // zero counters
__global__ void k_prep(const float* __restrict__ Wx, const float* __restrict__ Wq,
                       const float* __restrict__ Wf, const float* __restrict__ Wg,
                       const float* __restrict__ Wu, const float* __restrict__ Wo,
                       const float* __restrict__ Wc,
                       const float* __restrict__ root, const float* __restrict__ fb,
                       f16* __restrict__ wxh, f16* __restrict__ wqh, f16* __restrict__ wfh,
                       f16* __restrict__ wgu, f16* __restrict__ woh, f16* __restrict__ wchp,
                       f16* __restrict__ rbh, f16* __restrict__ fbh,
                       int* __restrict__ c1, int* __restrict__ c2)
{
    int i = blockIdx.x * 256 + threadIdx.x;
    if (i < CWX) {
        wxh[i] = __float2half_rn(Wx[i]);
    } else if (i < CWQ) {
        int j = i - CWX; wqh[j] = __float2half_rn(Wq[j]);
    } else if (i < CWF) {
        int j = i - CWQ; wfh[j] = __float2half_rn(Wf[j]);
    } else if (i < CWGU) {
        int j = i - CWF;
        int r = j / (2 * HIDP), cc = j % (2 * HIDP);
        int hu = cc >> 1;
        float v = 0.f;
        if (hu < HIDN) v = (cc & 1) ? Wu[r * HIDN + hu] : Wg[r * HIDN + hu];
        wgu[j] = __float2half_rn(v);
    } else if (i < CWO) {
        int j = i - CWGU; int r = j / 512;
        woh[j] = __float2half_rn((r < HIDN) ? Wo[j] : 0.f);
    } else if (i < CWC) {
        int j = i - CWO; int r = j >> 10, cc = j & 1023;
        int head = cc >> 7, c0 = cc & 127;
        wchp[j] = __float2half_rn((c0 < 64) ? Wc[r * 512 + head * 64 + c0] : 0.f);
    } else if (i < CRT) {
        long idx = (long)(i - CWC) * 4;
        float4 v = ld4(root + idx);
        f16 h[4];
        h[0] = __float2half_rn(v.x); h[1] = __float2half_rn(v.y);
        h[2] = __float2half_rn(v.z); h[3] = __float2half_rn(v.w);
        *reinterpret_cast<uint64_t*>(rbh + idx) = *reinterpret_cast<uint64_t*>(h);
    } else if (i < CFB) {
        long idx = (long)(i - CRT) * 4;
        float4 v = ld4(fb + idx);
        f16 h[4];
        h[0] = __float2half_rn(v.x); h[1] = __float2half_rn(v.y);
        h[2] = __float2half_rn(v.z); h[3] = __float2half_rn(v.w);
        *reinterpret_cast<uint64_t*>(fbh + idx) = *reinterpret_cast<uint64_t*>(h);
    } else if (i < CZ) {
        int j = i - CFB;
        c1[j] = 0; c2[j] = 0;
    }
}

// ---------------- CSR build ----------------
__global__ void k_hist2(const int* __restrict__ e1i, const int* __restrict__ e2i,
                        int* __restrict__ c1, int* __restrict__ c2) {
    int e = blockIdx.x * 256 + threadIdx.x;
    if (e < E1N) {
        atomicAdd(&c1[e1i[e]], 1);
        atomicAdd(&c2[e2i[e]], 1);
    }
}

__global__ void k_scan2(const int* __restrict__ c1, int* __restrict__ o1, int* __restrict__ u1,
                        const int* __restrict__ c2, int* __restrict__ o2, int* __restrict__ u2) {
    const int* cnt = blockIdx.x ? c2 : c1;
    int* off = blockIdx.x ? o2 : o1;
    int* cur = blockIdx.x ? u2 : u1;
    __shared__ int wsum[32];
    int t = threadIdx.x;
    int base = t * 16;
    int loc[16];
    int s = 0;
    #pragma unroll
    for (int i = 0; i < 16; i++) { loc[i] = s; s += cnt[base + i]; }
    int lane = t & 31, wd = t >> 5;
    int v = s;
    #pragma unroll
    for (int o = 1; o < 32; o <<= 1) {
        int u = __shfl_up_sync(0xffffffffu, v, o);
        if (lane >= o) v += u;
    }
    if (lane == 31) wsum[wd] = v;
    __syncthreads();
    if (wd == 0) {
        int wv = wsum[lane];
        #pragma unroll
        for (int o = 1; o < 32; o <<= 1) {
            int u = __shfl_up_sync(0xffffffffu, wv, o);
            if (lane >= o) wv += u;
        }
        wsum[lane] = wv;
    }
    __syncthreads();
    int prefix = (v - s) + (wd > 0 ? wsum[wd - 1] : 0);
    #pragma unroll
    for (int i = 0; i < 16; i++) {
        int o = prefix + loc[i];
        off[base + i] = o;
        cur[base + i] = o;
    }
    if (t == 1023) off[NN] = prefix + s;
}

__global__ void k_bucket2(const int* __restrict__ e1i, int* __restrict__ u1, int* __restrict__ p1,
                          const int* __restrict__ e2i, int* __restrict__ u2, int* __restrict__ p2) {
    int e = blockIdx.x * 256 + threadIdx.x;
    if (e < E1N) {
        int pos = atomicAdd(&u1[e1i[e]], 1);
        p1[pos] = e;
        int pos2 = atomicAdd(&u2[e2i[e]], 1);
        p2[pos2] = e;
    }
}

// ---- phase-1 gather, scores inline, fp16 fb ----
__global__ void k_gather1(const int* __restrict__ off, const int* __restrict__ perm,
                          const int* __restrict__ ej,
                          const float* __restrict__ a_src, const float* __restrict__ a_tgt,
                          const float* __restrict__ b_attn,
                          const f16* __restrict__ fbh16,
                          f16* __restrict__ x8h, float* __restrict__ den)
{
    const int n = blockIdx.x;
    const int t = threadIdx.x;     // 128
    const int dg = (t & 63) * 4;
    const int hb = (t >> 6) * 4;
    __shared__ int sj[128];
    float acc[4][4];
    #pragma unroll
    for (int a = 0; a < 4; a++)
        #pragma unroll
        for (int b = 0; b < 4; b++) acc[a][b] = 0.f;
    float dw0 = 0.f, dw1 = 0.f, dw2 = 0.f, dw3 = 0.f;

    float4 at4 = ld4(a_tgt + (size_t)n * 8 + hb);
    float4 b4  = ld4(b_attn + hb);
    at4.x += b4.x; at4.y += b4.y; at4.z += b4.z; at4.w += b4.w;

    const int s0 = off[n], s1 = off[n + 1];
    for (int p0 = s0; p0 < s1; p0 += 128) {
        int m = s1 - p0; if (m > 128) m = 128;
        __syncthreads();
        if (t < m) sj[t] = ej[perm[p0 + t]];
        __syncthreads();
        for (int q = 0; q < m; q++) {
            int j = sj[q];
            float4 as4 = ld4(a_src + (size_t)j * 8 + hb);
            float s0f = as4.x + at4.x; s0f = s0f > 0.f ? s0f : 0.2f * s0f;
            float s1f = as4.y + at4.y; s1f = s1f > 0.f ? s1f : 0.2f * s1f;
            float s2f = as4.z + at4.z; s2f = s2f > 0.f ? s2f : 0.2f * s2f;
            float s3f = as4.w + at4.w; s3f = s3f > 0.f ? s3f : 0.2f * s3f;
            float w0 = expf(s0f), w1 = expf(s1f), w2 = expf(s2f), w3 = expf(s3f);
            float4 v4 = ld4h(fbh16 + (size_t)j * 256 + dg);
            acc[0][0] += w0*v4.x; acc[0][1] += w0*v4.y; acc[0][2] += w0*v4.z; acc[0][3] += w0*v4.w;
            acc[1][0] += w1*v4.x; acc[1][1] += w1*v4.y; acc[1][2] += w1*v4.z; acc[1][3] += w1*v4.w;
            acc[2][0] += w2*v4.x; acc[2][1] += w2*v4.y; acc[2][2] += w2*v4.z; acc[2][3] += w2*v4.w;
            acc[3][0] += w3*v4.x; acc[3][1] += w3*v4.y; acc[3][2] += w3*v4.z; acc[3][3] += w3*v4.w;
            dw0 += w0; dw1 += w1; dw2 += w2; dw3 += w3;
        }
    }
    #pragma unroll
    for (int hh = 0; hh < 4; hh++) {
        size_t base = ((size_t)(hb + hh) * NN + n) * 256 + dg;
        f16 h[4];
        h[0] = __float2half_rn(acc[hh][0]); h[1] = __float2half_rn(acc[hh][1]);
        h[2] = __float2half_rn(acc[hh][2]); h[3] = __float2half_rn(acc[hh][3]);
        *reinterpret_cast<uint64_t*>(x8h + base) = *reinterpret_cast<uint64_t*>(h);
    }
    if ((t & 63) == 0) {
        float4 d4 = make_float4(dw0, dw1, dw2, dw3);
        *reinterpret_cast<float4*>(den + (size_t)n * 8 + hb) = d4;
    }
}

// ---- phase-2 fused gather ----
__global__ void k_gather2f(const int* __restrict__ off, const int* __restrict__ perm,
                           const int* __restrict__ ej, const float* __restrict__ attr,
                           const float* __restrict__ q, const f16* __restrict__ kh,
                           const f16* __restrict__ vh,
                           float* __restrict__ agg, float* __restrict__ den)
{
    const int n = blockIdx.x;
    const int t = threadIdx.x;           // 128
    const int h = t >> 4;
    const int c = t * 4;
    const int dg = (t & 15) * 4;
    __shared__ int sj[128];
    __shared__ int se[128];
    float4 qr = ld4(q + (size_t)n * 512 + c);
    float4 acc = make_float4(0.f, 0.f, 0.f, 0.f);
    float dsum = 0.f;
    const int s0 = off[n], s1 = off[n + 1];
    for (int p0 = s0; p0 < s1; p0 += 128) {
        int m = s1 - p0; if (m > 128) m = 128;
        __syncthreads();
        if (t < m) {
            int e = perm[p0 + t];
            se[t] = e;
            sj[t] = ej[e];
        }
        __syncthreads();
        for (int qq = 0; qq < m; qq++) {
            int j = sj[qq], e = se[qq];
            float4 a4 = ld4(attr + (size_t)e * 64 + dg);
            float4 k4 = ld4h(kh + (size_t)j * 512 + c);
            float p = qr.x * k4.x * a4.x + qr.y * k4.y * a4.y
                    + qr.z * k4.z * a4.z + qr.w * k4.w * a4.w;
            p += __shfl_xor_sync(0xffffffffu, p, 1);
            p += __shfl_xor_sync(0xffffffffu, p, 2);
            p += __shfl_xor_sync(0xffffffffu, p, 4);
            p += __shfl_xor_sync(0xffffffffu, p, 8);
            float ww = expf(p * 0.125f);
            float4 v4 = ld4h(vh + (size_t)j * 512 + c);
            acc.x += ww * v4.x; acc.y += ww * v4.y;
            acc.z += ww * v4.z; acc.w += ww * v4.w;
            dsum += ww;
        }
    }
    *reinterpret_cast<float4*>(agg + (size_t)n * 512 + c) = acc;
    if ((t & 15) == 0) den[n * 8 + h] = dsum;
}

// ---------------- merged skinny projections ----------------
__global__ void k_proj8_both(const float* __restrict__ fb, const float* __restrict__ rc,
                             const float* __restrict__ W,
                             float* __restrict__ a_src, float* __restrict__ a_tgt)
{
    __shared__ float Wsh[256 * 8];
    int t = threadIdx.x;
    const bool second = blockIdx.x >= (MM / 8);
    const float* Wsrc = second ? (W + 256 * 8) : W;
    for (int idx = t; idx < 2048; idx += 256) Wsh[idx] = Wsrc[idx];
    __syncthreads();
    int warp = t >> 5, lane = t & 31;
    long rb = second ? ((long)(blockIdx.x - MM / 8) * 8) : ((long)blockIdx.x * 8);
    long row = rb + warp;
    const float* a = (second ? rc : fb) + row * 256;
    float* outp = second ? a_tgt : a_src;
    float acc[8] = {0.f,0.f,0.f,0.f,0.f,0.f,0.f,0.f};
    for (int kk = lane; kk < 256; kk += 32) {
        float av = a[kk];
        #pragma unroll
        for (int h = 0; h < 8; h++) acc[h] += av * Wsh[kk * 8 + h];
    }
    #pragma unroll
    for (int h = 0; h < 8; h++)
        #pragma unroll
        for (int off = 16; off; off >>= 1)
            acc[h] += __shfl_xor_sync(0xffffffffu, acc[h], off);
    if (lane == 0) {
        #pragma unroll
        for (int h = 0; h < 8; h++) outp[row * 8 + h] = acc[h];
    }
}

// ---------------- rmsnorms ----------------
__global__ void k_rmsnorm1(const float* __restrict__ base, const float* __restrict__ num,
                           const float* __restrict__ den, const float* __restrict__ a_tgt,
                           const float* __restrict__ b_attn, const float* __restrict__ bc,
                           const float* __restrict__ g,
                           float* __restrict__ out, f16* __restrict__ oh) {
    int n = blockIdx.x;
    int t = threadIdx.x;
    float v[4]; float ss = 0.f;
    #pragma unroll
    for (int u2 = 0; u2 < 4; u2++) {
        int c = t + u2 * 128;
        int h = c >> 6;
        float s = a_tgt[n * 8 + h] + b_attn[h];
        s = s > 0.f ? s : 0.2f * s;
        float e0 = expf(s);
        float d = den[n * 8 + h] + e0;
        size_t idx = (size_t)n * 512 + c;
        float bval = base[idx];
        float add = (num[idx] + den[n * 8 + h] * bc[c] + e0 * bval) / d;
        float val = bval + add;
        v[u2] = val; ss += val * val;
    }
    #pragma unroll
    for (int off = 16; off; off >>= 1) ss += __shfl_xor_sync(0xffffffffu, ss, off);
    __shared__ float red[4];
    if ((t & 31) == 0) red[t >> 5] = ss;
    __syncthreads();
    float tot = red[0] + red[1] + red[2] + red[3];
    float r = rsqrtf(tot * (1.0f / 512.0f) + 1e-6f);
    #pragma unroll
    for (int u2 = 0; u2 < 4; u2++) {
        int c = t + u2 * 128;
        float o = v[u2] * r * g[c];
        size_t idx = (size_t)n * 512 + c;
        out[idx] = o;
        oh[idx] = __float2half_rn(o);
    }
}

__global__ void k_rmsnorm(const float* __restrict__ base, const float* __restrict__ num,
                          const float* __restrict__ den, const float* __restrict__ g,
                          float* __restrict__ out, f16* __restrict__ oh) {
    int n = blockIdx.x;
    int t = threadIdx.x;
    float v[4]; float ss = 0.f;
    #pragma unroll
    for (int u2 = 0; u2 < 4; u2++) {
        int c = t + u2 * 128;
        float a = num[(size_t)n * 512 + c];
        float add;
        if (den) { float d = den[n * 8 + (c >> 6)]; add = (d != 0.f) ? a / d : 0.f; }
        else add = a;
        float val = base[(size_t)n * 512 + c] + add;
        v[u2] = val; ss += val * val;
    }
    #pragma unroll
    for (int off = 16; off; off >>= 1) ss += __shfl_xor_sync(0xffffffffu, ss, off);
    __shared__ float red[4];
    if ((t & 31) == 0) red[t >> 5] = ss;
    __syncthreads();
    float tot = red[0] + red[1] + red[2] + red[3];
    float r = rsqrtf(tot * (1.0f / 512.0f) + 1e-6f);
    #pragma unroll
    for (int u2 = 0; u2 < 4; u2++) {
        int c = t + u2 * 128;
        float o = v[u2] * r * g[c];
        size_t idx = (size_t)n * 512 + c;
        out[idx] = o;
        if (oh) oh[idx] = __float2half_rn(o);
    }
}

// ---------------- host ----------------
#define SYM(p, s) cudaGetSymbolAddress((void**)&(p), s)

extern "C" void kernel_launch(void* const* d_in, const int* in_sizes, int n_in,
                              void* d_out, int out_size) {
    (void)in_sizes; (void)n_in; (void)out_size;
    const float* root   = (const float*)d_in[0];
    const float* fb     = (const float*)d_in[1];
    const int*   fbi    = (const int*)d_in[2];
    const int*   e1j = fbi;       const int* e1i = fbi + E1N;
    const float* fmaps  = (const float*)d_in[3];
    const int*   r2f    = (const int*)d_in[4];
    const int*   rei    = (const int*)d_in[5];
    const int*   e2j = rei;       const int* e2i = rei + E2N;
    const float* attr   = (const float*)d_in[6];
    const float* W_c2x  = (const float*)d_in[7];
    const float* b_c2x  = (const float*)d_in[8];
    const float* W_x2c  = (const float*)d_in[9];
    const float* b_x2c  = (const float*)d_in[10];
    const float* W_attn = (const float*)d_in[11];
    const float* b_attn = (const float*)d_in[12];
    const float* W_qkv  = (const float*)d_in[13];
    const float* b_qkv  = (const float*)d_in[14];
    const float* W_gate = (const float*)d_in[15];
    const float* W_up   = (const float*)d_in[16];
    const float* W_out  = (const float*)d_in[17];
    const float* W_fr   = (const float*)d_in[18];
    const float* b_fr   = (const float*)d_in[19];
    const float* gn     = (const float*)d_in[20];
    const float* gr     = (const float*)d_in[21];
    const float* gf     = (const float*)d_in[22];

    float* outx = (float*)d_out;
    float* outf = outx + (size_t)NN * ENCD;

    float *p_root_ctx, *p_a_src, *p_a_tgt, *p_den1, *p_agg1, *p_x1;
    float *p_q, *p_den2, *p_agg2, *p_x2, *p_o;
    SYM(p_root_ctx, s_root_ctx); SYM(p_a_src, s_a_src); SYM(p_a_tgt, s_a_tgt);
    SYM(p_den1, s_den1);
    SYM(p_agg1, s_agg1);         SYM(p_x1, s_x1);
    SYM(p_q, s_q);
    SYM(p_den2, s_den2); SYM(p_agg2, s_agg2); SYM(p_x2, s_x2);
    SYM(p_o, s_o);

    int *cnt1,*off1,*cur1,*perm1,*cnt2,*off2,*cur2,*perm2;
    SYM(cnt1, s_cnt1); SYM(off1, s_off1); SYM(cur1, s_cur1); SYM(perm1, s_perm1);
    SYM(cnt2, s_cnt2); SYM(off2, s_off2); SYM(cur2, s_cur2); SYM(perm2, s_perm2);

    f16 *rbh,*fbh,*x8h,*x1h,*kh,*vh,*x2h,*gsh,*xfh;
    f16 *wxh,*wchp,*wqh,*wgu,*woh,*wfh;
    SYM(rbh, s_rbh); SYM(fbh, s_fbh); SYM(x8h, s_x8h);
    SYM(x1h, s_x1h); SYM(kh, s_kh); SYM(vh, s_vh);
    SYM(x2h, s_x2h); SYM(gsh, s_gsh); SYM(xfh, s_xfh);
    SYM(wxh, s_wxh); SYM(wchp, s_wchp); SYM(wqh, s_wqh);
    SYM(wgu, s_wgu); SYM(woh, s_woh); SYM(wfh, s_wfh);

    cudaFuncSetAttribute((const void*)hgemm<0,false>, cudaFuncAttributeMaxDynamicSharedMemorySize, SMEM_T1);
    cudaFuncSetAttribute((const void*)hgemm<1,false>, cudaFuncAttributeMaxDynamicSharedMemorySize, SMEM_T1);
    cudaFuncSetAttribute((const void*)hgemm<2,true>,  cudaFuncAttributeMaxDynamicSharedMemorySize, SMEM_T1);
    cudaFuncSetAttribute((const void*)hgemm<4,false>, cudaFuncAttributeMaxDynamicSharedMemorySize, SMEM_T1);
    cudaFuncSetAttribute((const void*)hgemm<5,false>, cudaFuncAttributeMaxDynamicSharedMemorySize, SMEM_T1);

    // ---- prologue: one mega prep launch (weights + inputs + zero) ----
    k_prep<<<(CZ + 255)/256, 256>>>(W_x2c, W_qkv, W_fr, W_gate, W_up, W_out, W_c2x,
                                    root, fb,
                                    wxh, wqh, wfh, wgu, woh, wchp,
                                    rbh, fbh, cnt1, cnt2);
    hgemm<0,false><<<dim3(2,128), 256, SMEM_T1>>>(rbh, wxh, b_x2c,
        p_root_ctx, nullptr, nullptr, nullptr, nullptr, DECD, ENCD);
    k_hist2<<<E1N/256, 256>>>(e1i, e2i, cnt1, cnt2);
    k_scan2<<<2, 1024>>>(cnt1, off1, cur1, cnt2, off2, cur2);
    k_bucket2<<<E1N/256, 256>>>(e1i, cur1, perm1, e2i, cur2, perm2);

    // ---- HGAT attention projections (merged) ----
    k_proj8_both<<<MM/8 + NN/8, 256>>>(fb, p_root_ctx, W_attn, p_a_src, p_a_tgt);

    // ---- HGAT: gather (scores inline, fp16 fb), hoisted GEMM ----
    k_gather1<<<NN, 128>>>(off1, perm1, e1j, p_a_src, p_a_tgt, b_attn, fbh,
        x8h, p_den1);
    hgemm<4,false><<<dim3(8,128), 256, SMEM_T1>>>(x8h, wchp, nullptr,
        p_agg1, nullptr, nullptr, nullptr, nullptr, 1024, DECD);
    k_rmsnorm1<<<NN, 128>>>(root, p_agg1, p_den1, p_a_tgt, b_attn, b_c2x,
        gn, p_x1, x1h);

    // ---- Self-MHA ----
    hgemm<1,false><<<dim3(12,128), 256, SMEM_T1>>>(x1h, wqh, b_qkv,
        p_q, (float*)kh, (float*)vh, nullptr, nullptr, 1536, ENCD);
    k_gather2f<<<NN, 128>>>(off2, perm2, e2j, attr, p_q, kh, vh, p_agg2, p_den2);
    k_rmsnorm<<<NN, 128>>>(p_x1, p_agg2, p_den2, gr, p_x2, x2h);

    // ---- SwiGLU FFN (gate/up interleaved, SwiGLU fused in epilogue) ----
    hgemm<5,false><<<dim3(2 * HIDP / 128, 128), 256, SMEM_T1>>>(x2h, wgu, nullptr,
        (float*)gsh, nullptr, nullptr, nullptr, nullptr, 2 * HIDP, ENCD);
    hgemm<0,false><<<dim3(4,128), 256, SMEM_T1>>>(gsh, woh, nullptr,
        p_o, nullptr, nullptr, nullptr, nullptr, ENCD, HIDP);
    k_rmsnorm<<<NN, 128>>>(p_x2, p_o, nullptr, gf, outx, xfh);

    // ---- fringe decode (1-term) ----
    hgemm<2,true><<<dim3(2,128), 256, SMEM_T1>>>(xfh, wfh, b_fr,
        outf, nullptr, nullptr, fmaps, r2f, DECD, ENCD);
}